// round 10
// baseline (speedup 1.0000x reference)
#include <cuda_runtime.h>
#include <cuda_bf16.h>
#include <cstdint>

#define NN 16384
#define EE 262144
#define H1C 256
#define DD 512
#define NEG_SLOPE 0.2f

// ---------------- device scratch ----------------
__device__ uint32_t g_xp  [NN * H1C];           // packed x
__device__ float    g_h0f [NN * H1C];           // relu(fc) fp32
__device__ uint32_t g_agAp[NN * H1C];           // packed agg head0
__device__ uint32_t g_agBp[NN * H1C];           // packed agg head1
__device__ float    g_h1fa[NN * H1C];           // h1 half0 fp32
__device__ float    g_h1fb[NN * H1C];           // h1 half1 fp32
__device__ uint32_t g_ag2p[(size_t)NN * DD];    // packed agg layer2
__device__ uint4 g_wfcp[(H1C / 4) * H1C];
__device__ uint4 g_w1ap[(H1C / 4) * H1C];
__device__ uint4 g_w1bp[(H1C / 4) * H1C];
__device__ uint4 g_w2p [(DD / 4) * DD];
__device__ float4 g_P1[H1C];    // {s0,s1,d0,d1} per k
__device__ float2 g_P2[DD];     // {s,d} per k

__device__ float g_al1[NN * 4];
__device__ float g_al2[NN * 2];
__device__ int   g_deg[NN];
__device__ int   g_cursor[NN];
__device__ int   g_off[NN + 1];
__device__ int   g_esrc[EE];
__device__ float g_alpha1[(size_t)EE * 2];
__device__ float g_salpha1[NN * 2];
__device__ float g_alpha2[EE];
__device__ float g_salpha2[NN];

// ---------------- split helper ----------------
__device__ __forceinline__ void split_pack(float x0, float x1,
                                           uint32_t& hi, uint32_t& lo) {
    __nv_bfloat16 h0 = __float2bfloat16_rn(x0);
    __nv_bfloat16 h1 = __float2bfloat16_rn(x1);
    hi = (uint32_t)__bfloat16_as_ushort(h0) |
         ((uint32_t)__bfloat16_as_ushort(h1) << 16);
    float l0 = x0 - __bfloat162float(h0);
    float l1 = x1 - __bfloat162float(h1);
    __nv_bfloat162 lp = __floats2bfloat162_rn(l0, l1);
    lo = *reinterpret_cast<const uint32_t*>(&lp);
}

// ---------------- pack kernels ----------------
__global__ void pack_a_kernel(const float* __restrict__ X,
                              uint32_t* __restrict__ P, int npairs) {
    int i = blockIdx.x * blockDim.x + threadIdx.x;
    if (i < npairs) {
        float2 v = *(const float2*)(X + 2 * (size_t)i);
        split_pack(v.x, v.y, P[2 * (size_t)i], P[2 * (size_t)i + 1]);
    }
}

__global__ void pack_b_kernel(const float* __restrict__ W,
                              uint4* __restrict__ P, int K, int N, int ldw) {
    int idx = blockIdx.x * blockDim.x + threadIdx.x;
    int total = (K / 4) * N;
    if (idx >= total) return;
    int c = idx / N;
    int n = idx - c * N;
    const float* wp = W + (size_t)(4 * c) * ldw + n;
    uint4 o;
    split_pack(wp[0], wp[ldw], o.x, o.y);
    split_pack(wp[2 * ldw], wp[3 * ldw], o.z, o.w);
    P[idx] = o;
}

// ---------------- projection kernels (warp-per-row, coalesced) ----------------
__global__ void proj1_kernel(const float* __restrict__ W1,
                             const float* __restrict__ a1s,
                             const float* __restrict__ a1d) {
    int k = (blockIdx.x * blockDim.x + threadIdx.x) >> 5;
    if (k >= H1C) return;
    int lane = threadIdx.x & 31;
    const float* wr = W1 + (size_t)k * DD;
    float s0 = 0.f, s1 = 0.f, d0 = 0.f, d1 = 0.f;
    for (int c = lane; c < H1C; c += 32) {
        float w0 = wr[c];
        float w1 = wr[H1C + c];
        s0 = fmaf(w0, a1s[c], s0);
        s1 = fmaf(w1, a1s[H1C + c], s1);
        d0 = fmaf(w0, a1d[c], d0);
        d1 = fmaf(w1, a1d[H1C + c], d1);
    }
    #pragma unroll
    for (int o = 16; o; o >>= 1) {
        s0 += __shfl_down_sync(0xffffffffu, s0, o);
        s1 += __shfl_down_sync(0xffffffffu, s1, o);
        d0 += __shfl_down_sync(0xffffffffu, d0, o);
        d1 += __shfl_down_sync(0xffffffffu, d1, o);
    }
    if (lane == 0) g_P1[k] = make_float4(s0, s1, d0, d1);
}

__global__ void proj2_kernel(const float* __restrict__ W2,
                             const float* __restrict__ a2s,
                             const float* __restrict__ a2d) {
    int k = (blockIdx.x * blockDim.x + threadIdx.x) >> 5;
    if (k >= DD) return;
    int lane = threadIdx.x & 31;
    const float* wr = W2 + (size_t)k * DD;
    float s = 0.f, d = 0.f;
    for (int c = lane; c < DD; c += 32) {
        float w = wr[c];
        s = fmaf(w, a2s[c], s);
        d = fmaf(w, a2d[c], d);
    }
    #pragma unroll
    for (int o = 16; o; o >>= 1) {
        s += __shfl_down_sync(0xffffffffu, s, o);
        d += __shfl_down_sync(0xffffffffu, d, o);
    }
    if (lane == 0) g_P2[k] = make_float2(s, d);
}

// ---------------- CSR ----------------
__global__ void zero_kernel() {
    int i = blockIdx.x * blockDim.x + threadIdx.x;
    if (i < NN) { g_deg[i] = 0; g_cursor[i] = 0; }
}
__global__ void count_kernel(const int* __restrict__ adj) {
    int i = blockIdx.x * blockDim.x + threadIdx.x;
    if (i < EE) atomicAdd(&g_deg[adj[EE + i]], 1);
}
__global__ void scan_kernel() {
    int t = threadIdx.x;
    int base_i = t * 64;
    int sum = 0;
    #pragma unroll 4
    for (int k = 0; k < 64; k++) sum += g_deg[base_i + k];
    __shared__ int part[256];
    part[t] = sum;
    __syncthreads();
    for (int s = 1; s < 256; s <<= 1) {
        int v = (t >= s) ? part[t - s] : 0;
        __syncthreads();
        part[t] += v;
        __syncthreads();
    }
    int run = (t > 0) ? part[t - 1] : 0;
    for (int k = 0; k < 64; k++) {
        g_off[base_i + k] = run;
        run += g_deg[base_i + k];
    }
    if (t == 255) g_off[NN] = run;
}
__global__ void scatter_kernel(const int* __restrict__ adj) {
    int i = blockIdx.x * blockDim.x + threadIdx.x;
    if (i < EE) {
        int src = adj[i];
        int dst = adj[EE + i];
        int p = g_off[dst] + atomicAdd(&g_cursor[dst], 1);
        g_esrc[p] = src;
    }
}

// ================= Tensor-core GEMM (bf16x3, cp.async pipeline) =================
// out = relu(A@B + bias), fp32, unit-stride ldc == N.
__device__ __forceinline__ int smw(int outer, int kw) {
    int line = outer >> 1;
    int M = ((line & 3) << 1) | ((line >> 2) & 1);
    int lc = ((outer & 1) << 2) + (kw >> 1);
    return line * 32 + (((lc ^ M) << 2) | ((kw & 1) << 1));
}

__device__ __forceinline__ void mma16816(float* d, const uint32_t* a,
                                         const uint32_t* b) {
    asm volatile(
        "mma.sync.aligned.m16n8k16.row.col.f32.bf16.bf16.f32 "
        "{%0,%1,%2,%3}, {%4,%5,%6,%7}, {%8,%9}, {%0,%1,%2,%3};\n"
        : "+f"(d[0]), "+f"(d[1]), "+f"(d[2]), "+f"(d[3])
        : "r"(a[0]), "r"(a[1]), "r"(a[2]), "r"(a[3]),
          "r"(b[0]), "r"(b[1]));
}

__device__ __forceinline__ uint32_t smem_u32(const void* p) {
    uint32_t a;
    asm("{ .reg .u64 t; cvta.to.shared.u64 t, %1; cvt.u32.u64 %0, t; }"
        : "=r"(a) : "l"(p));
    return a;
}
__device__ __forceinline__ void cp16(uint32_t dst, const void* src) {
    asm volatile("cp.async.cg.shared.global [%0], [%1], 16;"
                 :: "r"(dst), "l"(src));
}
#define CP_COMMIT() asm volatile("cp.async.commit_group;" ::: "memory")
#define STG_BYTES 16384
#define NSTG 4

__device__ __forceinline__ void fill_stage(
    const uint32_t* __restrict__ Ap, const uint4* __restrict__ Bp,
    int brow, int bcol, int K, int N, int k0, int tid, uint32_t sbase)
{
    int c4 = tid & 3;
    #pragma unroll
    for (int f = 0; f < 2; f++) {
        int row = (tid >> 2) + 64 * f;
        cp16(sbase + 4 * smw(row, 2 * c4),
             Ap + (size_t)(brow + row) * K + k0 + 4 * c4);
    }
    int tc = tid >> 6;
    int m  = tid & 63;
    const uint4* bp = Bp + (size_t)((k0 >> 2) + tc) * N + bcol + 2 * m;
    uint32_t bB = sbase + 8192;
    cp16(bB + 4 * smw(2 * m,     2 * tc), bp);
    cp16(bB + 4 * smw(2 * m + 1, 2 * tc), bp + 1);
}

__global__ __launch_bounds__(256, 2) void tgemm_kernel(
    const uint32_t* __restrict__ Ap, const uint4* __restrict__ Bp,
    const float* __restrict__ bias, float* __restrict__ C,
    int M, int N, int K)
{
    extern __shared__ uint32_t dynsm[];
    const uint32_t sb = smem_u32(dynsm);

    const int tid  = threadIdx.x;
    const int lane = tid & 31;
    const int wid  = tid >> 5;
    const int wm   = wid & 1;
    const int wn   = wid >> 1;
    const int brow = blockIdx.y * 128;
    const int bcol = blockIdx.x * 128;

    float acc[4][4][4];
    #pragma unroll
    for (int i = 0; i < 4; i++)
        #pragma unroll
        for (int j = 0; j < 4; j++)
            #pragma unroll
            for (int q = 0; q < 4; q++) acc[i][j][q] = 0.f;

    const int iters = K >> 4;

    #pragma unroll
    for (int s = 0; s < NSTG - 1; s++) {
        if (s < iters) {
            fill_stage(Ap, Bp, brow, bcol, K, N, s << 4, tid, sb + s * STG_BYTES);
            CP_COMMIT();
        }
    }

    const int c  = lane & 3;
    const int r4 = lane >> 2;
    const int offA0 = smw(r4, c);
    const int offA1 = smw(8 + r4, c);
    const int offA2 = smw(r4, c + 4);
    const int offA3 = smw(8 + r4, c + 4);

    for (int it = 0; it < iters; ++it) {
        int rem = iters - 1 - it;
        if (rem >= 2)      asm volatile("cp.async.wait_group 2;" ::: "memory");
        else if (rem == 1) asm volatile("cp.async.wait_group 1;" ::: "memory");
        else               asm volatile("cp.async.wait_group 0;" ::: "memory");
        __syncthreads();

        uint32_t* buf  = dynsm + (it & (NSTG - 1)) * 4096;
        uint32_t* Abuf = buf;
        uint32_t* Bbuf = buf + 2048;

        uint2 bfr[4][2];
        #pragma unroll
        for (int ni = 0; ni < 4; ni++) {
            int base = wn * 512;
            bfr[ni][0] = *(const uint2*)&Bbuf[base + smw(ni * 8 + r4, c)];
            bfr[ni][1] = *(const uint2*)&Bbuf[base + smw(ni * 8 + r4, c + 4)];
        }
        #pragma unroll
        for (int mi = 0; mi < 4; mi++) {
            int base = (wm * 64 + mi * 16) * 16;
            uint2 a0 = *(const uint2*)&Abuf[base + offA0];
            uint2 a1 = *(const uint2*)&Abuf[base + offA1];
            uint2 a2 = *(const uint2*)&Abuf[base + offA2];
            uint2 a3 = *(const uint2*)&Abuf[base + offA3];
            uint32_t ah[4] = {a0.x, a1.x, a2.x, a3.x};
            uint32_t al[4] = {a0.y, a1.y, a2.y, a3.y};
            #pragma unroll
            for (int ni = 0; ni < 4; ni++) {
                uint32_t bh[2] = {bfr[ni][0].x, bfr[ni][1].x};
                uint32_t bl[2] = {bfr[ni][0].y, bfr[ni][1].y};
                mma16816(acc[mi][ni], ah, bh);
                mma16816(acc[mi][ni], ah, bl);
                mma16816(acc[mi][ni], al, bh);
            }
        }

        if (it + NSTG - 1 < iters) {
            fill_stage(Ap, Bp, brow, bcol, K, N, (it + NSTG - 1) << 4, tid,
                       sb + ((it + NSTG - 1) & (NSTG - 1)) * STG_BYTES);
            CP_COMMIT();
        }
    }

    #pragma unroll
    for (int mi = 0; mi < 4; mi++) {
        int row = brow + wm * 64 + mi * 16 + r4;
        #pragma unroll
        for (int ni = 0; ni < 4; ni++) {
            int col = bcol + wn * 32 + ni * 8 + 2 * c;
            float2 bb = *(const float2*)(bias + col);
            float2 v0, v1;
            v0.x = fmaxf(acc[mi][ni][0] + bb.x, 0.f);
            v0.y = fmaxf(acc[mi][ni][1] + bb.y, 0.f);
            v1.x = fmaxf(acc[mi][ni][2] + bb.x, 0.f);
            v1.y = fmaxf(acc[mi][ni][3] + bb.y, 0.f);
            *(float2*)(C + (size_t)row * N + col)       = v0;
            *(float2*)(C + (size_t)(row + 8) * N + col) = v1;
        }
    }
}

// ---------------- attention scalars (h-dot-projection) ----------------
__global__ void al1_kernel() {
    int n = (blockIdx.x * blockDim.x + threadIdx.x) >> 5;
    if (n >= NN) return;
    int lane = threadIdx.x & 31;
    const float4* row = (const float4*)(g_h0f + (size_t)n * H1C);
    float s0 = 0.f, s1 = 0.f, d0 = 0.f, d1 = 0.f;
    for (int c = lane; c < 64; c += 32) {
        float4 v = row[c];
        float4 p0 = g_P1[4 * c + 0];
        float4 p1 = g_P1[4 * c + 1];
        float4 p2 = g_P1[4 * c + 2];
        float4 p3 = g_P1[4 * c + 3];
        s0 += v.x * p0.x + v.y * p1.x + v.z * p2.x + v.w * p3.x;
        s1 += v.x * p0.y + v.y * p1.y + v.z * p2.y + v.w * p3.y;
        d0 += v.x * p0.z + v.y * p1.z + v.z * p2.z + v.w * p3.z;
        d1 += v.x * p0.w + v.y * p1.w + v.z * p2.w + v.w * p3.w;
    }
    #pragma unroll
    for (int o = 16; o; o >>= 1) {
        s0 += __shfl_down_sync(0xffffffffu, s0, o);
        s1 += __shfl_down_sync(0xffffffffu, s1, o);
        d0 += __shfl_down_sync(0xffffffffu, d0, o);
        d1 += __shfl_down_sync(0xffffffffu, d1, o);
    }
    if (lane == 0) ((float4*)g_al1)[n] = make_float4(s0, s1, d0, d1);
}

__global__ void al2_kernel() {
    int n = (blockIdx.x * blockDim.x + threadIdx.x) >> 5;
    if (n >= NN) return;
    int lane = threadIdx.x & 31;
    const float4* ra = (const float4*)(g_h1fa + (size_t)n * H1C);
    const float4* rb = (const float4*)(g_h1fb + (size_t)n * H1C);
    float s = 0.f, d = 0.f;
    for (int c = lane; c < 64; c += 32) {
        float4 v = ra[c];
        float2 p0 = g_P2[4 * c], p1 = g_P2[4 * c + 1];
        float2 p2 = g_P2[4 * c + 2], p3 = g_P2[4 * c + 3];
        s += v.x * p0.x + v.y * p1.x + v.z * p2.x + v.w * p3.x;
        d += v.x * p0.y + v.y * p1.y + v.z * p2.y + v.w * p3.y;
        float4 w = rb[c];
        float2 q0 = g_P2[H1C + 4 * c], q1 = g_P2[H1C + 4 * c + 1];
        float2 q2 = g_P2[H1C + 4 * c + 2], q3 = g_P2[H1C + 4 * c + 3];
        s += w.x * q0.x + w.y * q1.x + w.z * q2.x + w.w * q3.x;
        d += w.x * q0.y + w.y * q1.y + w.z * q2.y + w.w * q3.y;
    }
    #pragma unroll
    for (int o = 16; o; o >>= 1) {
        s += __shfl_down_sync(0xffffffffu, s, o);
        d += __shfl_down_sync(0xffffffffu, d, o);
    }
    if (lane == 0) ((float2*)g_al2)[n] = make_float2(s, d);
}

__device__ __forceinline__ float lrelu(float x) {
    return x > 0.f ? x : NEG_SLOPE * x;
}

// ---------------- edge softmax (R9: 1 random pass + 2 sequential) ----------------
__global__ void alpha1_kernel() {
    int n = (blockIdx.x * blockDim.x + threadIdx.x) >> 5;
    if (n >= NN) return;
    int lane = threadIdx.x & 31;
    int o = g_off[n];
    int cnt = g_off[n + 1] - o;
    float dd0 = g_al1[n * 4 + 2];
    float dd1 = g_al1[n * 4 + 3];

    float s0m = -1e30f, s1m = -1e30f;
    for (int i = lane; i <= cnt; i += 32) {
        int s = (i < cnt) ? g_esrc[o + i] : n;
        float2 sv = *(const float2*)(g_al1 + s * 4);
        s0m = fmaxf(s0m, sv.x);
        s1m = fmaxf(s1m, sv.y);
        if (i < cnt) *(float2*)(g_alpha1 + (size_t)(o + i) * 2) = sv;
    }
    #pragma unroll
    for (int x = 16; x; x >>= 1) {
        s0m = fmaxf(s0m, __shfl_xor_sync(0xffffffffu, s0m, x));
        s1m = fmaxf(s1m, __shfl_xor_sync(0xffffffffu, s1m, x));
    }
    float m0 = lrelu(s0m + dd0);
    float m1 = lrelu(s1m + dd1);
    __syncwarp();

    float sum0 = 0.f, sum1 = 0.f;
    for (int i = lane; i <= cnt; i += 32) {
        float2 sv = (i < cnt) ? *(const float2*)(g_alpha1 + (size_t)(o + i) * 2)
                              : *(const float2*)(g_al1 + n * 4);
        sum0 += expf(lrelu(sv.x + dd0) - m0);
        sum1 += expf(lrelu(sv.y + dd1) - m1);
    }
    #pragma unroll
    for (int x = 16; x; x >>= 1) {
        sum0 += __shfl_xor_sync(0xffffffffu, sum0, x);
        sum1 += __shfl_xor_sync(0xffffffffu, sum1, x);
    }
    float inv0 = 1.f / (sum0 + 1e-16f);
    float inv1 = 1.f / (sum1 + 1e-16f);

    for (int i = lane; i <= cnt; i += 32) {
        float2 sv = (i < cnt) ? *(const float2*)(g_alpha1 + (size_t)(o + i) * 2)
                              : *(const float2*)(g_al1 + n * 4);
        float a0 = expf(lrelu(sv.x + dd0) - m0) * inv0;
        float a1 = expf(lrelu(sv.y + dd1) - m1) * inv1;
        if (i < cnt) {
            *(float2*)(g_alpha1 + (size_t)(o + i) * 2) = make_float2(a0, a1);
        } else {
            g_salpha1[n * 2 + 0] = a0;
            g_salpha1[n * 2 + 1] = a1;
        }
    }
}

__global__ void alpha2_kernel() {
    int n = (blockIdx.x * blockDim.x + threadIdx.x) >> 5;
    if (n >= NN) return;
    int lane = threadIdx.x & 31;
    int o = g_off[n];
    int cnt = g_off[n + 1] - o;
    float dd = g_al2[n * 2 + 1];

    float sm = -1e30f;
    for (int i = lane; i <= cnt; i += 32) {
        int s = (i < cnt) ? g_esrc[o + i] : n;
        float sv = g_al2[s * 2];
        sm = fmaxf(sm, sv);
        if (i < cnt) g_alpha2[o + i] = sv;
    }
    #pragma unroll
    for (int x = 16; x; x >>= 1)
        sm = fmaxf(sm, __shfl_xor_sync(0xffffffffu, sm, x));
    float m = lrelu(sm + dd);
    __syncwarp();

    float sum = 0.f;
    for (int i = lane; i <= cnt; i += 32) {
        float sv = (i < cnt) ? g_alpha2[o + i] : g_al2[n * 2];
        sum += expf(lrelu(sv + dd) - m);
    }
    #pragma unroll
    for (int x = 16; x; x >>= 1)
        sum += __shfl_xor_sync(0xffffffffu, sum, x);
    float inv = 1.f / (sum + 1e-16f);

    for (int i = lane; i <= cnt; i += 32) {
        float sv = (i < cnt) ? g_alpha2[o + i] : g_al2[n * 2];
        float a = expf(lrelu(sv + dd) - m) * inv;
        if (i < cnt) g_alpha2[o + i] = a;
        else g_salpha2[n] = a;
    }
}

// ---------------- aggregate-first gathers ----------------
// Layer 1: gather h0 rows (1 KB), dual-head accumulate -> packed aggA/aggB
__global__ __launch_bounds__(64) void agg1x_kernel() {
    int n = blockIdx.x;
    int tid = threadIdx.x;           // float4 column 0..63
    int o = g_off[n];
    int cnt = g_off[n + 1] - o;

    __shared__ int    ssrc[64];
    __shared__ float2 sal[64];

    float4 a0 = make_float4(0.f, 0.f, 0.f, 0.f);
    float4 a1 = make_float4(0.f, 0.f, 0.f, 0.f);
    for (int base = 0; base < cnt; base += 64) {
        int m = min(64, cnt - base);
        if (tid < m) {
            int e = o + base + tid;
            ssrc[tid] = g_esrc[e];
            sal[tid] = *(const float2*)(g_alpha1 + (size_t)e * 2);
        }
        __syncthreads();
        for (int j = 0; j < m; j++) {
            float2 al = sal[j];
            float4 v = ((const float4*)(g_h0f + (size_t)ssrc[j] * H1C))[tid];
            a0.x = fmaf(al.x, v.x, a0.x); a0.y = fmaf(al.x, v.y, a0.y);
            a0.z = fmaf(al.x, v.z, a0.z); a0.w = fmaf(al.x, v.w, a0.w);
            a1.x = fmaf(al.y, v.x, a1.x); a1.y = fmaf(al.y, v.y, a1.y);
            a1.z = fmaf(al.y, v.z, a1.z); a1.w = fmaf(al.y, v.w, a1.w);
        }
        __syncthreads();
    }
    {
        float2 al = *(const float2*)(g_salpha1 + n * 2);
        float4 v = ((const float4*)(g_h0f + (size_t)n * H1C))[tid];
        a0.x = fmaf(al.x, v.x, a0.x); a0.y = fmaf(al.x, v.y, a0.y);
        a0.z = fmaf(al.x, v.z, a0.z); a0.w = fmaf(al.x, v.w, a0.w);
        a1.x = fmaf(al.y, v.x, a1.x); a1.y = fmaf(al.y, v.y, a1.y);
        a1.z = fmaf(al.y, v.z, a1.z); a1.w = fmaf(al.y, v.w, a1.w);
    }
    uint4 w;
    split_pack(a0.x, a0.y, w.x, w.y);
    split_pack(a0.z, a0.w, w.z, w.w);
    *(uint4*)(g_agAp + (size_t)n * H1C + 4 * tid) = w;
    split_pack(a1.x, a1.y, w.x, w.y);
    split_pack(a1.z, a1.w, w.z, w.w);
    *(uint4*)(g_agBp + (size_t)n * H1C + 4 * tid) = w;
}

// Layer 2: gather h1 rows (two 1 KB halves) -> packed agg2 (K=512 row)
__global__ __launch_bounds__(128) void agg2x_kernel() {
    int n = blockIdx.x;
    int tid = threadIdx.x;
    int half = tid >> 6;             // 0: h1fa, 1: h1fb
    int idx  = tid & 63;             // float4 column
    const float* hsrc = half ? g_h1fb : g_h1fa;
    int o = g_off[n];
    int cnt = g_off[n + 1] - o;

    __shared__ int   ssrc[128];
    __shared__ float sal[128];

    float4 acc = make_float4(0.f, 0.f, 0.f, 0.f);
    for (int base = 0; base < cnt; base += 128) {
        int m = min(128, cnt - base);
        if (tid < m) {
            ssrc[tid] = g_esrc[o + base + tid];
            sal[tid] = g_alpha2[o + base + tid];
        }
        __syncthreads();
        for (int j = 0; j < m; j++) {
            float a = sal[j];
            float4 v = ((const float4*)(hsrc + (size_t)ssrc[j] * H1C))[idx];
            acc.x = fmaf(a, v.x, acc.x);
            acc.y = fmaf(a, v.y, acc.y);
            acc.z = fmaf(a, v.z, acc.z);
            acc.w = fmaf(a, v.w, acc.w);
        }
        __syncthreads();
    }
    {
        float a = g_salpha2[n];
        float4 v = ((const float4*)(hsrc + (size_t)n * H1C))[idx];
        acc.x = fmaf(a, v.x, acc.x);
        acc.y = fmaf(a, v.y, acc.y);
        acc.z = fmaf(a, v.z, acc.z);
        acc.w = fmaf(a, v.w, acc.w);
    }
    uint4 w;
    split_pack(acc.x, acc.y, w.x, w.y);
    split_pack(acc.z, acc.w, w.z, w.w);
    // element offset = half*256 + 4*idx -> word offset = half*256*... (2 words/2 elems): 256*half + 4*idx words... row 512 words
    *(uint4*)(g_ag2p + (size_t)n * DD + half * H1C + 4 * idx) = w;
}

// ---------------- launcher ----------------
template <typename T>
static T* sym_p(const void* sym) {
    void* p = nullptr;
    cudaGetSymbolAddress(&p, sym);
    return (T*)p;
}

extern "C" void kernel_launch(void* const* d_in, const int* in_sizes, int n_in,
                              void* d_out, int out_size) {
    const float* x      = (const float*)d_in[0];
    const int*   adj    = (const int*)d_in[1];
    const float* W_fc   = (const float*)d_in[2];
    const float* b_fc   = (const float*)d_in[3];
    const float* W1     = (const float*)d_in[4];
    const float* a1_src = (const float*)d_in[5];
    const float* a1_dst = (const float*)d_in[6];
    const float* b1     = (const float*)d_in[7];
    const float* W2     = (const float*)d_in[8];
    const float* a2_src = (const float*)d_in[9];
    const float* a2_dst = (const float*)d_in[10];
    const float* b2     = (const float*)d_in[11];
    float* out = (float*)d_out;

    uint32_t* p_xp   = sym_p<uint32_t>(g_xp);
    float*    p_h0f  = sym_p<float>(g_h0f);
    uint32_t* p_agA  = sym_p<uint32_t>(g_agAp);
    uint32_t* p_agB  = sym_p<uint32_t>(g_agBp);
    float*    p_h1fa = sym_p<float>(g_h1fa);
    float*    p_h1fb = sym_p<float>(g_h1fb);
    uint32_t* p_ag2  = sym_p<uint32_t>(g_ag2p);
    uint4*    p_wfc  = sym_p<uint4>(g_wfcp);
    uint4*    p_w1a  = sym_p<uint4>(g_w1ap);
    uint4*    p_w1b  = sym_p<uint4>(g_w1bp);
    uint4*    p_w2   = sym_p<uint4>(g_w2p);

    const int dyn = NSTG * STG_BYTES;   // 64 KB
    cudaFuncSetAttribute(tgemm_kernel,
                         cudaFuncAttributeMaxDynamicSharedMemorySize, dyn);

    // packs + projections
    pack_a_kernel<<<(NN * H1C / 2 + 255) / 256, 256>>>(x, p_xp, NN * H1C / 2);
    pack_b_kernel<<<((H1C / 4) * H1C + 255) / 256, 256>>>(W_fc, p_wfc, H1C, H1C, H1C);
    pack_b_kernel<<<((H1C / 4) * H1C + 255) / 256, 256>>>(W1, p_w1a, H1C, H1C, DD);
    pack_b_kernel<<<((H1C / 4) * H1C + 255) / 256, 256>>>(W1 + H1C, p_w1b, H1C, H1C, DD);
    pack_b_kernel<<<((DD / 4) * DD + 255) / 256, 256>>>(W2, p_w2, DD, DD, DD);
    proj1_kernel<<<(H1C * 32 + 255) / 256, 256>>>(W1, a1_src, a1_dst);
    proj2_kernel<<<(DD * 32 + 255) / 256, 256>>>(W2, a2_src, a2_dst);

    // CSR
    zero_kernel<<<(NN + 255) / 256, 256>>>();
    count_kernel<<<(EE + 255) / 256, 256>>>(adj);
    scan_kernel<<<1, 256>>>();
    scatter_kernel<<<(EE + 255) / 256, 256>>>(adj);

    // fc + relu -> h0 fp32
    tgemm_kernel<<<dim3(H1C / 128, NN / 128), 256, dyn>>>(
        p_xp, p_wfc, b_fc, p_h0f, NN, H1C, H1C);

    // layer-1 attention + aggregate-first
    al1_kernel<<<(NN * 32 + 255) / 256, 256>>>();
    alpha1_kernel<<<(NN * 32 + 255) / 256, 256>>>();
    agg1x_kernel<<<NN, 64>>>();

    // h1 halves = relu(aggH @ W1head + b1 half), fp32, ldc=256
    tgemm_kernel<<<dim3(H1C / 128, NN / 128), 256, dyn>>>(
        p_agA, p_w1a, b1, p_h1fa, NN, H1C, H1C);
    tgemm_kernel<<<dim3(H1C / 128, NN / 128), 256, dyn>>>(
        p_agB, p_w1b, b1 + H1C, p_h1fb, NN, H1C, H1C);

    // layer-2 attention + aggregate-first
    al2_kernel<<<(NN * 32 + 255) / 256, 256>>>();
    alpha2_kernel<<<(NN * 32 + 255) / 256, 256>>>();
    agg2x_kernel<<<NN, 128>>>();

    // out = relu(agg2 @ W2 + b2)
    tgemm_kernel<<<dim3(DD / 128, NN / 128), 256, dyn>>>(
        p_ag2, p_w2, b2, out, NN, DD, DD);
}

// round 11
// speedup vs baseline: 1.2092x; 1.2092x over previous
#include <cuda_runtime.h>
#include <cuda_bf16.h>
#include <cstdint>

#define NN 16384
#define EE 262144
#define H1C 256
#define DD 512
#define NEG_SLOPE 0.2f

// ---------------- device scratch ----------------
__device__ uint32_t g_xp [NN * H1C];
__device__ uint32_t g_h0p[NN * H1C];
__device__ uint32_t g_h1p[(size_t)NN * DD];
__device__ float    g_g1[(size_t)NN * DD];
__device__ float    g_g2[(size_t)NN * DD];
__device__ uint4 g_wfcp[(H1C / 4) * H1C];
__device__ uint4 g_w1p [(H1C / 4) * DD];
__device__ uint4 g_w2p [(DD / 4) * DD];

__device__ float g_al1[NN * 4];
__device__ float g_al2[NN * 2];
__device__ int   g_deg[NN];
__device__ int   g_cursor[NN];
__device__ int   g_off[NN + 1];
__device__ int   g_esrc[EE];
__device__ float g_alpha1[(size_t)EE * 2];
__device__ float g_salpha1[NN * 2];
__device__ float g_alpha2[EE];
__device__ float g_salpha2[NN];

// ---------------- side stream for graph-parallel branch ----------------
static cudaStream_t g_side = nullptr;
static cudaEvent_t  g_evF = nullptr, g_evJ = nullptr;
namespace {
struct StreamInit {
    StreamInit() {
        cudaStreamCreateWithFlags(&g_side, cudaStreamNonBlocking);
        cudaEventCreateWithFlags(&g_evF, cudaEventDisableTiming);
        cudaEventCreateWithFlags(&g_evJ, cudaEventDisableTiming);
    }
};
static StreamInit g_si;
}

// ---------------- split helpers ----------------
__device__ __forceinline__ void split_pack(float x0, float x1,
                                           uint32_t& hi, uint32_t& lo) {
    __nv_bfloat16 h0 = __float2bfloat16_rn(x0);
    __nv_bfloat16 h1 = __float2bfloat16_rn(x1);
    hi = (uint32_t)__bfloat16_as_ushort(h0) |
         ((uint32_t)__bfloat16_as_ushort(h1) << 16);
    float l0 = x0 - __bfloat162float(h0);
    float l1 = x1 - __bfloat162float(h1);
    __nv_bfloat162 lp = __floats2bfloat162_rn(l0, l1);
    lo = *reinterpret_cast<const uint32_t*>(&lp);
}

// ---------------- pack kernels ----------------
__global__ void pack_a_kernel(const float* __restrict__ X,
                              uint32_t* __restrict__ P, int npairs) {
    int i = blockIdx.x * blockDim.x + threadIdx.x;
    if (i < npairs) {
        float2 v = *(const float2*)(X + 2 * (size_t)i);
        split_pack(v.x, v.y, P[2 * (size_t)i], P[2 * (size_t)i + 1]);
    }
}

__global__ void pack_b_kernel(const float* __restrict__ W,
                              uint4* __restrict__ P, int K, int N) {
    int idx = blockIdx.x * blockDim.x + threadIdx.x;
    int total = (K / 4) * N;
    if (idx >= total) return;
    int c = idx / N;
    int n = idx - c * N;
    const float* wp = W + (size_t)(4 * c) * N + n;
    uint4 o;
    split_pack(wp[0], wp[N], o.x, o.y);
    split_pack(wp[2 * N], wp[3 * N], o.z, o.w);
    P[idx] = o;
}

// ---------------- CSR construction ----------------
__global__ void zero_kernel() {
    int i = blockIdx.x * blockDim.x + threadIdx.x;
    if (i < NN) { g_deg[i] = 0; g_cursor[i] = 0; }
}
__global__ void count_kernel(const int* __restrict__ adj) {
    int i = blockIdx.x * blockDim.x + threadIdx.x;
    if (i < EE) atomicAdd(&g_deg[adj[EE + i]], 1);
}
__global__ void scan_kernel() {
    int t = threadIdx.x;
    int base_i = t * 64;
    int sum = 0;
    #pragma unroll 4
    for (int k = 0; k < 64; k++) sum += g_deg[base_i + k];
    __shared__ int part[256];
    part[t] = sum;
    __syncthreads();
    for (int s = 1; s < 256; s <<= 1) {
        int v = (t >= s) ? part[t - s] : 0;
        __syncthreads();
        part[t] += v;
        __syncthreads();
    }
    int run = (t > 0) ? part[t - 1] : 0;
    for (int k = 0; k < 64; k++) {
        g_off[base_i + k] = run;
        run += g_deg[base_i + k];
    }
    if (t == 255) g_off[NN] = run;
}
__global__ void scatter_kernel(const int* __restrict__ adj) {
    int i = blockIdx.x * blockDim.x + threadIdx.x;
    if (i < EE) {
        int src = adj[i];
        int dst = adj[EE + i];
        int p = g_off[dst] + atomicAdd(&g_cursor[dst], 1);
        g_esrc[p] = src;
    }
}

// ================= Tensor-core GEMM (bf16x3, cp.async pipeline) =================
__device__ __forceinline__ int smw(int outer, int kw) {
    int line = outer >> 1;
    int M = ((line & 3) << 1) | ((line >> 2) & 1);
    int lc = ((outer & 1) << 2) + (kw >> 1);
    return line * 32 + (((lc ^ M) << 2) | ((kw & 1) << 1));
}

__device__ __forceinline__ void mma16816(float* d, const uint32_t* a,
                                         const uint32_t* b) {
    asm volatile(
        "mma.sync.aligned.m16n8k16.row.col.f32.bf16.bf16.f32 "
        "{%0,%1,%2,%3}, {%4,%5,%6,%7}, {%8,%9}, {%0,%1,%2,%3};\n"
        : "+f"(d[0]), "+f"(d[1]), "+f"(d[2]), "+f"(d[3])
        : "r"(a[0]), "r"(a[1]), "r"(a[2]), "r"(a[3]),
          "r"(b[0]), "r"(b[1]));
}

__device__ __forceinline__ uint32_t smem_u32(const void* p) {
    uint32_t a;
    asm("{ .reg .u64 t; cvta.to.shared.u64 t, %1; cvt.u32.u64 %0, t; }"
        : "=r"(a) : "l"(p));
    return a;
}
__device__ __forceinline__ void cp16(uint32_t dst, const void* src) {
    asm volatile("cp.async.cg.shared.global [%0], [%1], 16;"
                 :: "r"(dst), "l"(src));
}
#define CP_COMMIT() asm volatile("cp.async.commit_group;" ::: "memory")
#define STG_BYTES 16384
#define NSTG 4

__device__ __forceinline__ void fill_stage(
    const uint32_t* __restrict__ Ap, const uint4* __restrict__ Bp,
    int brow, int bcol, int K, int N, int k0, int tid, uint32_t sbase)
{
    int c4 = tid & 3;
    #pragma unroll
    for (int f = 0; f < 2; f++) {
        int row = (tid >> 2) + 64 * f;
        cp16(sbase + 4 * smw(row, 2 * c4),
             Ap + (size_t)(brow + row) * K + k0 + 4 * c4);
    }
    int tc = tid >> 6;
    int m  = tid & 63;
    const uint4* bp = Bp + (size_t)((k0 >> 2) + tc) * N + bcol + 2 * m;
    uint32_t bB = sbase + 8192;
    cp16(bB + 4 * smw(2 * m,     2 * tc), bp);
    cp16(bB + 4 * smw(2 * m + 1, 2 * tc), bp + 1);
}

// OUT_MODE: 0 = fp32 plain, 1 = packed split-bf16 with bias+relu
template <int OUT_MODE>
__global__ __launch_bounds__(256, 2) void tgemm_p_kernel(
    const uint32_t* __restrict__ Ap, const uint4* __restrict__ Bp,
    const float* __restrict__ bias, void* __restrict__ Cout,
    int M, int N, int K)
{
    extern __shared__ uint32_t dynsm[];
    const uint32_t sb = smem_u32(dynsm);

    const int tid  = threadIdx.x;
    const int lane = tid & 31;
    const int wid  = tid >> 5;
    const int wm   = wid & 1;
    const int wn   = wid >> 1;
    const int brow = blockIdx.y * 128;
    const int bcol = blockIdx.x * 128;

    float acc[4][4][4];
    #pragma unroll
    for (int i = 0; i < 4; i++)
        #pragma unroll
        for (int j = 0; j < 4; j++)
            #pragma unroll
            for (int q = 0; q < 4; q++) acc[i][j][q] = 0.f;

    const int iters = K >> 4;

    #pragma unroll
    for (int s = 0; s < NSTG - 1; s++) {
        if (s < iters) {
            fill_stage(Ap, Bp, brow, bcol, K, N, s << 4, tid, sb + s * STG_BYTES);
            CP_COMMIT();
        }
    }

    const int c  = lane & 3;
    const int r4 = lane >> 2;
    const int offA0 = smw(r4, c);
    const int offA1 = smw(8 + r4, c);
    const int offA2 = smw(r4, c + 4);
    const int offA3 = smw(8 + r4, c + 4);

    for (int it = 0; it < iters; ++it) {
        int rem = iters - 1 - it;
        if (rem >= 2)      asm volatile("cp.async.wait_group 2;" ::: "memory");
        else if (rem == 1) asm volatile("cp.async.wait_group 1;" ::: "memory");
        else               asm volatile("cp.async.wait_group 0;" ::: "memory");
        __syncthreads();

        uint32_t* buf  = dynsm + (it & (NSTG - 1)) * 4096;
        uint32_t* Abuf = buf;
        uint32_t* Bbuf = buf + 2048;

        uint2 bfr[4][2];
        #pragma unroll
        for (int ni = 0; ni < 4; ni++) {
            int base = wn * 512;
            bfr[ni][0] = *(const uint2*)&Bbuf[base + smw(ni * 8 + r4, c)];
            bfr[ni][1] = *(const uint2*)&Bbuf[base + smw(ni * 8 + r4, c + 4)];
        }
        #pragma unroll
        for (int mi = 0; mi < 4; mi++) {
            int base = (wm * 64 + mi * 16) * 16;
            uint2 a0 = *(const uint2*)&Abuf[base + offA0];
            uint2 a1 = *(const uint2*)&Abuf[base + offA1];
            uint2 a2 = *(const uint2*)&Abuf[base + offA2];
            uint2 a3 = *(const uint2*)&Abuf[base + offA3];
            uint32_t ah[4] = {a0.x, a1.x, a2.x, a3.x};
            uint32_t al[4] = {a0.y, a1.y, a2.y, a3.y};
            #pragma unroll
            for (int ni = 0; ni < 4; ni++) {
                uint32_t bh[2] = {bfr[ni][0].x, bfr[ni][1].x};
                uint32_t bl[2] = {bfr[ni][0].y, bfr[ni][1].y};
                mma16816(acc[mi][ni], ah, bh);
                mma16816(acc[mi][ni], ah, bl);
                mma16816(acc[mi][ni], al, bh);
            }
        }

        if (it + NSTG - 1 < iters) {
            fill_stage(Ap, Bp, brow, bcol, K, N, (it + NSTG - 1) << 4, tid,
                       sb + ((it + NSTG - 1) & (NSTG - 1)) * STG_BYTES);
            CP_COMMIT();
        }
    }

    #pragma unroll
    for (int mi = 0; mi < 4; mi++) {
        int row = brow + wm * 64 + mi * 16 + r4;
        #pragma unroll
        for (int ni = 0; ni < 4; ni++) {
            int col = bcol + wn * 32 + ni * 8 + 2 * c;
            float2 v0 = make_float2(acc[mi][ni][0], acc[mi][ni][1]);
            float2 v1 = make_float2(acc[mi][ni][2], acc[mi][ni][3]);
            if (OUT_MODE == 1) {
                float2 bb = *(const float2*)(bias + col);
                v0.x = fmaxf(v0.x + bb.x, 0.f); v0.y = fmaxf(v0.y + bb.y, 0.f);
                v1.x = fmaxf(v1.x + bb.x, 0.f); v1.y = fmaxf(v1.y + bb.y, 0.f);
                uint2 w0, w1;
                split_pack(v0.x, v0.y, w0.x, w0.y);
                split_pack(v1.x, v1.y, w1.x, w1.y);
                uint32_t* P = (uint32_t*)Cout;
                *(uint2*)(P + (size_t)row * N + col)       = w0;
                *(uint2*)(P + (size_t)(row + 8) * N + col) = w1;
            } else {
                float* C = (float*)Cout;
                *(float2*)(C + (size_t)row * N + col)       = v0;
                *(float2*)(C + (size_t)(row + 8) * N + col) = v1;
            }
        }
    }
}

// ---------------- attention scalars ----------------
__global__ void al1_kernel(const float* __restrict__ a_src,
                           const float* __restrict__ a_dst)
{
    int gw = (blockIdx.x * blockDim.x + threadIdx.x) >> 5;
    if (gw >= NN) return;
    int lane = threadIdx.x & 31;
    const float4* row = (const float4*)(g_g1 + (size_t)gw * DD);
    const float4* as4 = (const float4*)a_src;
    const float4* ad4 = (const float4*)a_dst;
    float s0 = 0.f, s1 = 0.f, d0 = 0.f, d1 = 0.f;
    for (int c = lane; c < 128; c += 32) {
        float4 v = row[c];
        float4 a = as4[c];
        float4 b = ad4[c];
        float sv = v.x * a.x + v.y * a.y + v.z * a.z + v.w * a.w;
        float dv = v.x * b.x + v.y * b.y + v.z * b.z + v.w * b.w;
        if (c < 64) { s0 += sv; d0 += dv; } else { s1 += sv; d1 += dv; }
    }
    #pragma unroll
    for (int o = 16; o; o >>= 1) {
        s0 += __shfl_down_sync(0xffffffffu, s0, o);
        s1 += __shfl_down_sync(0xffffffffu, s1, o);
        d0 += __shfl_down_sync(0xffffffffu, d0, o);
        d1 += __shfl_down_sync(0xffffffffu, d1, o);
    }
    if (lane == 0) {
        g_al1[gw * 4 + 0] = s0;
        g_al1[gw * 4 + 1] = s1;
        g_al1[gw * 4 + 2] = d0;
        g_al1[gw * 4 + 3] = d1;
    }
}

__global__ void al2_kernel(const float* __restrict__ a_src,
                           const float* __restrict__ a_dst)
{
    int gw = (blockIdx.x * blockDim.x + threadIdx.x) >> 5;
    if (gw >= NN) return;
    int lane = threadIdx.x & 31;
    const float4* row = (const float4*)(g_g2 + (size_t)gw * DD);
    const float4* as4 = (const float4*)a_src;
    const float4* ad4 = (const float4*)a_dst;
    float s = 0.f, d = 0.f;
    for (int c = lane; c < 128; c += 32) {
        float4 v = row[c];
        float4 a = as4[c];
        float4 b = ad4[c];
        s += v.x * a.x + v.y * a.y + v.z * a.z + v.w * a.w;
        d += v.x * b.x + v.y * b.y + v.z * b.z + v.w * b.w;
    }
    #pragma unroll
    for (int o = 16; o; o >>= 1) {
        s += __shfl_down_sync(0xffffffffu, s, o);
        d += __shfl_down_sync(0xffffffffu, d, o);
    }
    if (lane == 0) {
        g_al2[gw * 2 + 0] = s;
        g_al2[gw * 2 + 1] = d;
    }
}

__device__ __forceinline__ float lrelu(float x) {
    return x > 0.f ? x : NEG_SLOPE * x;
}

// ---------------- edge softmax (warp per node, incl. self loop) ----------------
__global__ void alpha1_kernel() {
    int n = (blockIdx.x * blockDim.x + threadIdx.x) >> 5;
    if (n >= NN) return;
    int lane = threadIdx.x & 31;
    int o = g_off[n];
    int cnt = g_off[n + 1] - o;
    float dd0 = g_al1[n * 4 + 2];
    float dd1 = g_al1[n * 4 + 3];

    float m0 = -1e30f, m1 = -1e30f;
    for (int i = lane; i <= cnt; i += 32) {
        int s = (i < cnt) ? g_esrc[o + i] : n;
        float e0 = lrelu(g_al1[s * 4 + 0] + dd0);
        float e1 = lrelu(g_al1[s * 4 + 1] + dd1);
        m0 = fmaxf(m0, e0);
        m1 = fmaxf(m1, e1);
    }
    #pragma unroll
    for (int x = 16; x; x >>= 1) {
        m0 = fmaxf(m0, __shfl_xor_sync(0xffffffffu, m0, x));
        m1 = fmaxf(m1, __shfl_xor_sync(0xffffffffu, m1, x));
    }
    float sum0 = 0.f, sum1 = 0.f;
    for (int i = lane; i <= cnt; i += 32) {
        int s = (i < cnt) ? g_esrc[o + i] : n;
        sum0 += expf(lrelu(g_al1[s * 4 + 0] + dd0) - m0);
        sum1 += expf(lrelu(g_al1[s * 4 + 1] + dd1) - m1);
    }
    #pragma unroll
    for (int x = 16; x; x >>= 1) {
        sum0 += __shfl_xor_sync(0xffffffffu, sum0, x);
        sum1 += __shfl_xor_sync(0xffffffffu, sum1, x);
    }
    float inv0 = 1.f / (sum0 + 1e-16f);
    float inv1 = 1.f / (sum1 + 1e-16f);
    for (int i = lane; i <= cnt; i += 32) {
        int s = (i < cnt) ? g_esrc[o + i] : n;
        float a0 = expf(lrelu(g_al1[s * 4 + 0] + dd0) - m0) * inv0;
        float a1 = expf(lrelu(g_al1[s * 4 + 1] + dd1) - m1) * inv1;
        if (i < cnt) {
            g_alpha1[(size_t)(o + i) * 2 + 0] = a0;
            g_alpha1[(size_t)(o + i) * 2 + 1] = a1;
        } else {
            g_salpha1[n * 2 + 0] = a0;
            g_salpha1[n * 2 + 1] = a1;
        }
    }
}

__global__ void alpha2_kernel() {
    int n = (blockIdx.x * blockDim.x + threadIdx.x) >> 5;
    if (n >= NN) return;
    int lane = threadIdx.x & 31;
    int o = g_off[n];
    int cnt = g_off[n + 1] - o;
    float dd = g_al2[n * 2 + 1];

    float m = -1e30f;
    for (int i = lane; i <= cnt; i += 32) {
        int s = (i < cnt) ? g_esrc[o + i] : n;
        m = fmaxf(m, lrelu(g_al2[s * 2] + dd));
    }
    #pragma unroll
    for (int x = 16; x; x >>= 1)
        m = fmaxf(m, __shfl_xor_sync(0xffffffffu, m, x));
    float sum = 0.f;
    for (int i = lane; i <= cnt; i += 32) {
        int s = (i < cnt) ? g_esrc[o + i] : n;
        sum += expf(lrelu(g_al2[s * 2] + dd) - m);
    }
    #pragma unroll
    for (int x = 16; x; x >>= 1)
        sum += __shfl_xor_sync(0xffffffffu, sum, x);
    float inv = 1.f / (sum + 1e-16f);
    for (int i = lane; i <= cnt; i += 32) {
        int s = (i < cnt) ? g_esrc[o + i] : n;
        float a = expf(lrelu(g_al2[s * 2] + dd) - m) * inv;
        if (i < cnt) g_alpha2[o + i] = a;
        else g_salpha2[n] = a;
    }
}

// ---------------- aggregation ----------------
__global__ __launch_bounds__(128) void agg1_kernel(const float* __restrict__ b1) {
    int n = blockIdx.x;
    int tid = threadIdx.x;
    int o = g_off[n];
    int cnt = g_off[n + 1] - o;
    int head = tid >> 6;

    __shared__ int   ssrc[128];
    __shared__ float sal[128 * 2];

    float4 acc = make_float4(0.f, 0.f, 0.f, 0.f);
    for (int base = 0; base < cnt; base += 128) {
        int m = min(128, cnt - base);
        if (tid < m) {
            ssrc[tid] = g_esrc[o + base + tid];
            sal[tid * 2 + 0] = g_alpha1[(size_t)(o + base + tid) * 2 + 0];
            sal[tid * 2 + 1] = g_alpha1[(size_t)(o + base + tid) * 2 + 1];
        }
        __syncthreads();
        for (int j = 0; j < m; j++) {
            float a = sal[j * 2 + head];
            const float4* r = (const float4*)(g_g1 + (size_t)ssrc[j] * DD);
            float4 v = r[tid];
            acc.x = fmaf(a, v.x, acc.x);
            acc.y = fmaf(a, v.y, acc.y);
            acc.z = fmaf(a, v.z, acc.z);
            acc.w = fmaf(a, v.w, acc.w);
        }
        __syncthreads();
    }
    {
        float a = g_salpha1[n * 2 + head];
        float4 v = ((const float4*)(g_g1 + (size_t)n * DD))[tid];
        acc.x = fmaf(a, v.x, acc.x);
        acc.y = fmaf(a, v.y, acc.y);
        acc.z = fmaf(a, v.z, acc.z);
        acc.w = fmaf(a, v.w, acc.w);
    }
    float4 bb = ((const float4*)b1)[tid];
    acc.x = fmaxf(acc.x + bb.x, 0.f);
    acc.y = fmaxf(acc.y + bb.y, 0.f);
    acc.z = fmaxf(acc.z + bb.z, 0.f);
    acc.w = fmaxf(acc.w + bb.w, 0.f);
    uint4 w;
    split_pack(acc.x, acc.y, w.x, w.y);
    split_pack(acc.z, acc.w, w.z, w.w);
    *(uint4*)(g_h1p + (size_t)n * DD + 4 * tid) = w;
}

__global__ __launch_bounds__(128) void agg2_kernel(const float* __restrict__ b2,
                                                   float* __restrict__ out) {
    int n = blockIdx.x;
    int tid = threadIdx.x;
    int o = g_off[n];
    int cnt = g_off[n + 1] - o;

    __shared__ int   ssrc[128];
    __shared__ float sal[128];

    float4 acc = make_float4(0.f, 0.f, 0.f, 0.f);
    for (int base = 0; base < cnt; base += 128) {
        int m = min(128, cnt - base);
        if (tid < m) {
            ssrc[tid] = g_esrc[o + base + tid];
            sal[tid] = g_alpha2[o + base + tid];
        }
        __syncthreads();
        for (int j = 0; j < m; j++) {
            float a = sal[j];
            const float4* r = (const float4*)(g_g2 + (size_t)ssrc[j] * DD);
            float4 v = r[tid];
            acc.x = fmaf(a, v.x, acc.x);
            acc.y = fmaf(a, v.y, acc.y);
            acc.z = fmaf(a, v.z, acc.z);
            acc.w = fmaf(a, v.w, acc.w);
        }
        __syncthreads();
    }
    {
        float a = g_salpha2[n];
        float4 v = ((const float4*)(g_g2 + (size_t)n * DD))[tid];
        acc.x = fmaf(a, v.x, acc.x);
        acc.y = fmaf(a, v.y, acc.y);
        acc.z = fmaf(a, v.z, acc.z);
        acc.w = fmaf(a, v.w, acc.w);
    }
    float4 bb = ((const float4*)b2)[tid];
    acc.x = fmaxf(acc.x + bb.x, 0.f);
    acc.y = fmaxf(acc.y + bb.y, 0.f);
    acc.z = fmaxf(acc.z + bb.z, 0.f);
    acc.w = fmaxf(acc.w + bb.w, 0.f);
    ((float4*)(out + (size_t)n * DD))[tid] = acc;
}

// ---------------- launcher ----------------
template <typename T>
static T* sym_p(const void* sym) {
    void* p = nullptr;
    cudaGetSymbolAddress(&p, sym);
    return (T*)p;
}

extern "C" void kernel_launch(void* const* d_in, const int* in_sizes, int n_in,
                              void* d_out, int out_size) {
    const float* x      = (const float*)d_in[0];
    const int*   adj    = (const int*)d_in[1];
    const float* W_fc   = (const float*)d_in[2];
    const float* b_fc   = (const float*)d_in[3];
    const float* W1     = (const float*)d_in[4];
    const float* a1_src = (const float*)d_in[5];
    const float* a1_dst = (const float*)d_in[6];
    const float* b1     = (const float*)d_in[7];
    const float* W2     = (const float*)d_in[8];
    const float* a2_src = (const float*)d_in[9];
    const float* a2_dst = (const float*)d_in[10];
    const float* b2     = (const float*)d_in[11];
    float* out = (float*)d_out;

    uint32_t* p_xp  = sym_p<uint32_t>(g_xp);
    uint32_t* p_h0p = sym_p<uint32_t>(g_h0p);
    uint32_t* p_h1p = sym_p<uint32_t>(g_h1p);
    float*    p_g1  = sym_p<float>(g_g1);
    float*    p_g2  = sym_p<float>(g_g2);
    uint4*    p_wfc = sym_p<uint4>(g_wfcp);
    uint4*    p_w1  = sym_p<uint4>(g_w1p);
    uint4*    p_w2  = sym_p<uint4>(g_w2p);

    const int dyn = NSTG * STG_BYTES;   // 64 KB
    cudaFuncSetAttribute(tgemm_p_kernel<0>,
                         cudaFuncAttributeMaxDynamicSharedMemorySize, dyn);
    cudaFuncSetAttribute(tgemm_p_kernel<1>,
                         cudaFuncAttributeMaxDynamicSharedMemorySize, dyn);

    // ---- fork: side branch (W2 pack + CSR build) runs parallel to main GEMM chain
    cudaEventRecord(g_evF, 0);
    cudaStreamWaitEvent(g_side, g_evF, 0);
    pack_b_kernel<<<((DD / 4) * DD + 255) / 256, 256, 0, g_side>>>(W2, p_w2, DD, DD);
    zero_kernel<<<(NN + 255) / 256, 256, 0, g_side>>>();
    count_kernel<<<(EE + 255) / 256, 256, 0, g_side>>>(adj);
    scan_kernel<<<1, 256, 0, g_side>>>();
    scatter_kernel<<<(EE + 255) / 256, 256, 0, g_side>>>(adj);
    cudaEventRecord(g_evJ, g_side);

    // ---- main branch
    pack_a_kernel<<<(NN * H1C / 2 + 255) / 256, 256>>>(x, p_xp, NN * H1C / 2);
    pack_b_kernel<<<((H1C / 4) * H1C + 255) / 256, 256>>>(W_fc, p_wfc, H1C, H1C);
    pack_b_kernel<<<((H1C / 4) * DD + 255) / 256, 256>>>(W1, p_w1, H1C, DD);

    // fc + relu -> packed h0
    {
        dim3 grid(H1C / 128, NN / 128);
        tgemm_p_kernel<1><<<grid, 256, dyn>>>(p_xp, p_wfc, b_fc, p_h0p, NN, H1C, H1C);
    }
    // g1 = h0 @ W1 (fp32)
    {
        dim3 grid(DD / 128, NN / 128);
        tgemm_p_kernel<0><<<grid, 256, dyn>>>(p_h0p, p_w1, nullptr, p_g1, NN, DD, H1C);
    }
    al1_kernel<<<(NN * 32 + 255) / 256, 256>>>(a1_src, a1_dst);

    // ---- join: CSR + W2 pack must be done before alpha1 / final GEMM
    cudaStreamWaitEvent(0, g_evJ, 0);

    alpha1_kernel<<<(NN * 32 + 255) / 256, 256>>>();
    agg1_kernel<<<NN, 128>>>(b1);          // -> packed h1

    // g2 = h1 @ W2 (fp32)
    {
        dim3 grid(DD / 128, NN / 128);
        tgemm_p_kernel<0><<<grid, 256, dyn>>>(p_h1p, p_w2, nullptr, p_g2, NN, DD, DD);
    }
    al2_kernel<<<(NN * 32 + 255) / 256, 256>>>(a2_src, a2_dst);
    alpha2_kernel<<<(NN * 32 + 255) / 256, 256>>>();
    agg2_kernel<<<NN, 128>>>(b2, out);
}

// round 12
// speedup vs baseline: 1.2619x; 1.0436x over previous
#include <cuda_runtime.h>
#include <cuda_bf16.h>
#include <cstdint>

#define NN 16384
#define EE 262144
#define H1C 256
#define DD 512
#define NEG_SLOPE 0.2f

// ---------------- device scratch ----------------
__device__ uint32_t g_xp [NN * H1C];
__device__ uint32_t g_h0p[NN * H1C];
__device__ uint32_t g_h1p[(size_t)NN * DD];
__device__ float    g_g1[(size_t)NN * DD];
__device__ float    g_g2[(size_t)NN * DD];
__device__ uint4 g_wfcp[(H1C / 4) * H1C];
__device__ uint4 g_w1p [(H1C / 4) * DD];
__device__ uint4 g_w2p [(DD / 4) * DD];
__device__ float4 g_P1[H1C];    // {s0,s1,d0,d1} per k
__device__ float2 g_P2[DD];     // {s,d} per k

__device__ float g_al1[NN * 4];
__device__ float g_al2[NN * 2];
__device__ __align__(16) int g_deg[NN];
__device__ int   g_cursor[NN];
__device__ __align__(16) int g_off[NN + 1];
__device__ int   g_esrc[EE];
__device__ float g_alpha1[(size_t)EE * 2];
__device__ float g_salpha1[NN * 2];
__device__ float g_alpha2[EE];
__device__ float g_salpha2[NN];

// ---------------- streams / events for graph-parallel branches ----------------
static cudaStream_t g_side = nullptr;
static cudaEvent_t g_evF = nullptr, g_evG1 = nullptr, g_evJ1 = nullptr;
static cudaEvent_t g_evA1 = nullptr, g_evJ2 = nullptr;
namespace {
struct StreamInit {
    StreamInit() {
        cudaStreamCreateWithFlags(&g_side, cudaStreamNonBlocking);
        cudaEventCreateWithFlags(&g_evF, cudaEventDisableTiming);
        cudaEventCreateWithFlags(&g_evG1, cudaEventDisableTiming);
        cudaEventCreateWithFlags(&g_evJ1, cudaEventDisableTiming);
        cudaEventCreateWithFlags(&g_evA1, cudaEventDisableTiming);
        cudaEventCreateWithFlags(&g_evJ2, cudaEventDisableTiming);
    }
};
static StreamInit g_si;
}

// ---------------- split helpers ----------------
__device__ __forceinline__ void split_pack(float x0, float x1,
                                           uint32_t& hi, uint32_t& lo) {
    __nv_bfloat16 h0 = __float2bfloat16_rn(x0);
    __nv_bfloat16 h1 = __float2bfloat16_rn(x1);
    hi = (uint32_t)__bfloat16_as_ushort(h0) |
         ((uint32_t)__bfloat16_as_ushort(h1) << 16);
    float l0 = x0 - __bfloat162float(h0);
    float l1 = x1 - __bfloat162float(h1);
    __nv_bfloat162 lp = __floats2bfloat162_rn(l0, l1);
    lo = *reinterpret_cast<const uint32_t*>(&lp);
}

__device__ __forceinline__ float bf_lo(uint32_t w) {
    return __bfloat162float(__ushort_as_bfloat16((unsigned short)(w & 0xffffu)));
}
__device__ __forceinline__ float bf_hi(uint32_t w) {
    return __bfloat162float(__ushort_as_bfloat16((unsigned short)(w >> 16)));
}

// ---------------- pack kernels ----------------
__global__ void pack_a_kernel(const float* __restrict__ X,
                              uint32_t* __restrict__ P, int npairs) {
    int i = blockIdx.x * blockDim.x + threadIdx.x;
    if (i < npairs) {
        float2 v = *(const float2*)(X + 2 * (size_t)i);
        split_pack(v.x, v.y, P[2 * (size_t)i], P[2 * (size_t)i + 1]);
    }
}

__global__ void pack_b_kernel(const float* __restrict__ W,
                              uint4* __restrict__ P, int K, int N) {
    int idx = blockIdx.x * blockDim.x + threadIdx.x;
    int total = (K / 4) * N;
    if (idx >= total) return;
    int c = idx / N;
    int n = idx - c * N;
    const float* wp = W + (size_t)(4 * c) * N + n;
    uint4 o;
    split_pack(wp[0], wp[N], o.x, o.y);
    split_pack(wp[2 * N], wp[3 * N], o.z, o.w);
    P[idx] = o;
}

// ---------------- projection kernels (warp per k-row) ----------------
__global__ void proj1_kernel(const float* __restrict__ W1,
                             const float* __restrict__ a1s,
                             const float* __restrict__ a1d) {
    int k = (blockIdx.x * blockDim.x + threadIdx.x) >> 5;
    if (k >= H1C) return;
    int lane = threadIdx.x & 31;
    const float* wr = W1 + (size_t)k * DD;
    float s0 = 0.f, s1 = 0.f, d0 = 0.f, d1 = 0.f;
    for (int c = lane; c < H1C; c += 32) {
        float w0 = wr[c];
        float w1 = wr[H1C + c];
        s0 = fmaf(w0, a1s[c], s0);
        s1 = fmaf(w1, a1s[H1C + c], s1);
        d0 = fmaf(w0, a1d[c], d0);
        d1 = fmaf(w1, a1d[H1C + c], d1);
    }
    #pragma unroll
    for (int o = 16; o; o >>= 1) {
        s0 += __shfl_down_sync(0xffffffffu, s0, o);
        s1 += __shfl_down_sync(0xffffffffu, s1, o);
        d0 += __shfl_down_sync(0xffffffffu, d0, o);
        d1 += __shfl_down_sync(0xffffffffu, d1, o);
    }
    if (lane == 0) g_P1[k] = make_float4(s0, s1, d0, d1);
}

__global__ void proj2_kernel(const float* __restrict__ W2,
                             const float* __restrict__ a2s,
                             const float* __restrict__ a2d) {
    int k = (blockIdx.x * blockDim.x + threadIdx.x) >> 5;
    if (k >= DD) return;
    int lane = threadIdx.x & 31;
    const float* wr = W2 + (size_t)k * DD;
    float s = 0.f, d = 0.f;
    for (int c = lane; c < DD; c += 32) {
        float w = wr[c];
        s = fmaf(w, a2s[c], s);
        d = fmaf(w, a2d[c], d);
    }
    #pragma unroll
    for (int o = 16; o; o >>= 1) {
        s += __shfl_down_sync(0xffffffffu, s, o);
        d += __shfl_down_sync(0xffffffffu, d, o);
    }
    if (lane == 0) g_P2[k] = make_float2(s, d);
}

// ---------------- CSR construction ----------------
__global__ void zero_kernel() {
    int i = blockIdx.x * blockDim.x + threadIdx.x;
    if (i < NN) { g_deg[i] = 0; g_cursor[i] = 0; }
}
__global__ void count_kernel(const int* __restrict__ adj) {
    int i = blockIdx.x * blockDim.x + threadIdx.x;
    if (i < EE) atomicAdd(&g_deg[adj[EE + i]], 1);
}
// vectorized single-block scan: int4 loads (MLP 16/thread), int4 prefix stores
__global__ void scan_kernel() {
    int t = threadIdx.x;   // 256 threads, 64 elems each
    int4 v[16];
    const int4* dp = (const int4*)g_deg + t * 16;
    #pragma unroll
    for (int k = 0; k < 16; k++) v[k] = dp[k];
    int sum = 0;
    #pragma unroll
    for (int k = 0; k < 16; k++) sum += v[k].x + v[k].y + v[k].z + v[k].w;
    __shared__ int part[256];
    part[t] = sum;
    __syncthreads();
    for (int s = 1; s < 256; s <<= 1) {
        int q = (t >= s) ? part[t - s] : 0;
        __syncthreads();
        part[t] += q;
        __syncthreads();
    }
    int run = (t > 0) ? part[t - 1] : 0;
    int4* op = (int4*)g_off + t * 16;
    #pragma unroll
    for (int k = 0; k < 16; k++) {
        int4 o;
        o.x = run; run += v[k].x;
        o.y = run; run += v[k].y;
        o.z = run; run += v[k].z;
        o.w = run; run += v[k].w;
        op[k] = o;
    }
    if (t == 255) g_off[NN] = run;
}
__global__ void scatter_kernel(const int* __restrict__ adj) {
    int i = blockIdx.x * blockDim.x + threadIdx.x;
    if (i < EE) {
        int src = adj[i];
        int dst = adj[EE + i];
        int p = g_off[dst] + atomicAdd(&g_cursor[dst], 1);
        g_esrc[p] = src;
    }
}

// ================= Tensor-core GEMM (bf16x3, cp.async pipeline) =================
__device__ __forceinline__ int smw(int outer, int kw) {
    int line = outer >> 1;
    int M = ((line & 3) << 1) | ((line >> 2) & 1);
    int lc = ((outer & 1) << 2) + (kw >> 1);
    return line * 32 + (((lc ^ M) << 2) | ((kw & 1) << 1));
}

__device__ __forceinline__ void mma16816(float* d, const uint32_t* a,
                                         const uint32_t* b) {
    asm volatile(
        "mma.sync.aligned.m16n8k16.row.col.f32.bf16.bf16.f32 "
        "{%0,%1,%2,%3}, {%4,%5,%6,%7}, {%8,%9}, {%0,%1,%2,%3};\n"
        : "+f"(d[0]), "+f"(d[1]), "+f"(d[2]), "+f"(d[3])
        : "r"(a[0]), "r"(a[1]), "r"(a[2]), "r"(a[3]),
          "r"(b[0]), "r"(b[1]));
}

__device__ __forceinline__ uint32_t smem_u32(const void* p) {
    uint32_t a;
    asm("{ .reg .u64 t; cvta.to.shared.u64 t, %1; cvt.u32.u64 %0, t; }"
        : "=r"(a) : "l"(p));
    return a;
}
__device__ __forceinline__ void cp16(uint32_t dst, const void* src) {
    asm volatile("cp.async.cg.shared.global [%0], [%1], 16;"
                 :: "r"(dst), "l"(src));
}
#define CP_COMMIT() asm volatile("cp.async.commit_group;" ::: "memory")
#define STG_BYTES 16384
#define NSTG 4

__device__ __forceinline__ void fill_stage(
    const uint32_t* __restrict__ Ap, const uint4* __restrict__ Bp,
    int brow, int bcol, int K, int N, int k0, int tid, uint32_t sbase)
{
    int c4 = tid & 3;
    #pragma unroll
    for (int f = 0; f < 2; f++) {
        int row = (tid >> 2) + 64 * f;
        cp16(sbase + 4 * smw(row, 2 * c4),
             Ap + (size_t)(brow + row) * K + k0 + 4 * c4);
    }
    int tc = tid >> 6;
    int m  = tid & 63;
    const uint4* bp = Bp + (size_t)((k0 >> 2) + tc) * N + bcol + 2 * m;
    uint32_t bB = sbase + 8192;
    cp16(bB + 4 * smw(2 * m,     2 * tc), bp);
    cp16(bB + 4 * smw(2 * m + 1, 2 * tc), bp + 1);
}

// OUT_MODE: 0 = fp32 plain, 1 = packed split-bf16 with bias+relu
template <int OUT_MODE>
__global__ __launch_bounds__(256, 2) void tgemm_p_kernel(
    const uint32_t* __restrict__ Ap, const uint4* __restrict__ Bp,
    const float* __restrict__ bias, void* __restrict__ Cout,
    int M, int N, int K)
{
    extern __shared__ uint32_t dynsm[];
    const uint32_t sb = smem_u32(dynsm);

    const int tid  = threadIdx.x;
    const int lane = tid & 31;
    const int wid  = tid >> 5;
    const int wm   = wid & 1;
    const int wn   = wid >> 1;
    const int brow = blockIdx.y * 128;
    const int bcol = blockIdx.x * 128;

    float acc[4][4][4];
    #pragma unroll
    for (int i = 0; i < 4; i++)
        #pragma unroll
        for (int j = 0; j < 4; j++)
            #pragma unroll
            for (int q = 0; q < 4; q++) acc[i][j][q] = 0.f;

    const int iters = K >> 4;

    #pragma unroll
    for (int s = 0; s < NSTG - 1; s++) {
        if (s < iters) {
            fill_stage(Ap, Bp, brow, bcol, K, N, s << 4, tid, sb + s * STG_BYTES);
            CP_COMMIT();
        }
    }

    const int c  = lane & 3;
    const int r4 = lane >> 2;
    const int offA0 = smw(r4, c);
    const int offA1 = smw(8 + r4, c);
    const int offA2 = smw(r4, c + 4);
    const int offA3 = smw(8 + r4, c + 4);

    for (int it = 0; it < iters; ++it) {
        int rem = iters - 1 - it;
        if (rem >= 2)      asm volatile("cp.async.wait_group 2;" ::: "memory");
        else if (rem == 1) asm volatile("cp.async.wait_group 1;" ::: "memory");
        else               asm volatile("cp.async.wait_group 0;" ::: "memory");
        __syncthreads();

        uint32_t* buf  = dynsm + (it & (NSTG - 1)) * 4096;
        uint32_t* Abuf = buf;
        uint32_t* Bbuf = buf + 2048;

        uint2 bfr[4][2];
        #pragma unroll
        for (int ni = 0; ni < 4; ni++) {
            int base = wn * 512;
            bfr[ni][0] = *(const uint2*)&Bbuf[base + smw(ni * 8 + r4, c)];
            bfr[ni][1] = *(const uint2*)&Bbuf[base + smw(ni * 8 + r4, c + 4)];
        }
        #pragma unroll
        for (int mi = 0; mi < 4; mi++) {
            int base = (wm * 64 + mi * 16) * 16;
            uint2 a0 = *(const uint2*)&Abuf[base + offA0];
            uint2 a1 = *(const uint2*)&Abuf[base + offA1];
            uint2 a2 = *(const uint2*)&Abuf[base + offA2];
            uint2 a3 = *(const uint2*)&Abuf[base + offA3];
            uint32_t ah[4] = {a0.x, a1.x, a2.x, a3.x};
            uint32_t al[4] = {a0.y, a1.y, a2.y, a3.y};
            #pragma unroll
            for (int ni = 0; ni < 4; ni++) {
                uint32_t bh[2] = {bfr[ni][0].x, bfr[ni][1].x};
                uint32_t bl[2] = {bfr[ni][0].y, bfr[ni][1].y};
                mma16816(acc[mi][ni], ah, bh);
                mma16816(acc[mi][ni], ah, bl);
                mma16816(acc[mi][ni], al, bh);
            }
        }

        if (it + NSTG - 1 < iters) {
            fill_stage(Ap, Bp, brow, bcol, K, N, (it + NSTG - 1) << 4, tid,
                       sb + ((it + NSTG - 1) & (NSTG - 1)) * STG_BYTES);
            CP_COMMIT();
        }
    }

    #pragma unroll
    for (int mi = 0; mi < 4; mi++) {
        int row = brow + wm * 64 + mi * 16 + r4;
        #pragma unroll
        for (int ni = 0; ni < 4; ni++) {
            int col = bcol + wn * 32 + ni * 8 + 2 * c;
            float2 v0 = make_float2(acc[mi][ni][0], acc[mi][ni][1]);
            float2 v1 = make_float2(acc[mi][ni][2], acc[mi][ni][3]);
            if (OUT_MODE == 1) {
                float2 bb = *(const float2*)(bias + col);
                v0.x = fmaxf(v0.x + bb.x, 0.f); v0.y = fmaxf(v0.y + bb.y, 0.f);
                v1.x = fmaxf(v1.x + bb.x, 0.f); v1.y = fmaxf(v1.y + bb.y, 0.f);
                uint2 w0, w1;
                split_pack(v0.x, v0.y, w0.x, w0.y);
                split_pack(v1.x, v1.y, w1.x, w1.y);
                uint32_t* P = (uint32_t*)Cout;
                *(uint2*)(P + (size_t)row * N + col)       = w0;
                *(uint2*)(P + (size_t)(row + 8) * N + col) = w1;
            } else {
                float* C = (float*)Cout;
                *(float2*)(C + (size_t)row * N + col)       = v0;
                *(float2*)(C + (size_t)(row + 8) * N + col) = v1;
            }
        }
    }
}

// ---------------- attention scalars from packed h via projections ----------------
__global__ void al1p_kernel() {
    int n = (blockIdx.x * blockDim.x + threadIdx.x) >> 5;
    if (n >= NN) return;
    int lane = threadIdx.x & 31;
    const uint2* row = (const uint2*)(g_h0p + (size_t)n * H1C);
    float s0 = 0.f, s1 = 0.f, d0 = 0.f, d1 = 0.f;
    for (int i = lane; i < 128; i += 32) {
        uint2 w = row[i];                 // w.x = hi pair, w.y = lo pair
        float x0 = bf_lo(w.x) + bf_lo(w.y);
        float x1 = bf_hi(w.x) + bf_hi(w.y);
        float4 p0 = g_P1[2 * i];
        float4 p1 = g_P1[2 * i + 1];
        s0 += x0 * p0.x + x1 * p1.x;
        s1 += x0 * p0.y + x1 * p1.y;
        d0 += x0 * p0.z + x1 * p1.z;
        d1 += x0 * p0.w + x1 * p1.w;
    }
    #pragma unroll
    for (int o = 16; o; o >>= 1) {
        s0 += __shfl_down_sync(0xffffffffu, s0, o);
        s1 += __shfl_down_sync(0xffffffffu, s1, o);
        d0 += __shfl_down_sync(0xffffffffu, d0, o);
        d1 += __shfl_down_sync(0xffffffffu, d1, o);
    }
    if (lane == 0) ((float4*)g_al1)[n] = make_float4(s0, s1, d0, d1);
}

__global__ void al2p_kernel() {
    int n = (blockIdx.x * blockDim.x + threadIdx.x) >> 5;
    if (n >= NN) return;
    int lane = threadIdx.x & 31;
    const uint2* row = (const uint2*)(g_h1p + (size_t)n * DD);
    float s = 0.f, d = 0.f;
    for (int i = lane; i < 256; i += 32) {
        uint2 w = row[i];
        float x0 = bf_lo(w.x) + bf_lo(w.y);
        float x1 = bf_hi(w.x) + bf_hi(w.y);
        float2 p0 = g_P2[2 * i];
        float2 p1 = g_P2[2 * i + 1];
        s += x0 * p0.x + x1 * p1.x;
        d += x0 * p0.y + x1 * p1.y;
    }
    #pragma unroll
    for (int o = 16; o; o >>= 1) {
        s += __shfl_down_sync(0xffffffffu, s, o);
        d += __shfl_down_sync(0xffffffffu, d, o);
    }
    if (lane == 0) ((float2*)g_al2)[n] = make_float2(s, d);
}

__device__ __forceinline__ float lrelu(float x) {
    return x > 0.f ? x : NEG_SLOPE * x;
}

// ---------------- edge softmax ----------------
__global__ void alpha1_kernel() {
    int n = (blockIdx.x * blockDim.x + threadIdx.x) >> 5;
    if (n >= NN) return;
    int lane = threadIdx.x & 31;
    int o = g_off[n];
    int cnt = g_off[n + 1] - o;
    float dd0 = g_al1[n * 4 + 2];
    float dd1 = g_al1[n * 4 + 3];

    float m0 = -1e30f, m1 = -1e30f;
    for (int i = lane; i <= cnt; i += 32) {
        int s = (i < cnt) ? g_esrc[o + i] : n;
        m0 = fmaxf(m0, lrelu(g_al1[s * 4 + 0] + dd0));
        m1 = fmaxf(m1, lrelu(g_al1[s * 4 + 1] + dd1));
    }
    #pragma unroll
    for (int x = 16; x; x >>= 1) {
        m0 = fmaxf(m0, __shfl_xor_sync(0xffffffffu, m0, x));
        m1 = fmaxf(m1, __shfl_xor_sync(0xffffffffu, m1, x));
    }
    float sum0 = 0.f, sum1 = 0.f;
    for (int i = lane; i <= cnt; i += 32) {
        int s = (i < cnt) ? g_esrc[o + i] : n;
        sum0 += expf(lrelu(g_al1[s * 4 + 0] + dd0) - m0);
        sum1 += expf(lrelu(g_al1[s * 4 + 1] + dd1) - m1);
    }
    #pragma unroll
    for (int x = 16; x; x >>= 1) {
        sum0 += __shfl_xor_sync(0xffffffffu, sum0, x);
        sum1 += __shfl_xor_sync(0xffffffffu, sum1, x);
    }
    float inv0 = 1.f / (sum0 + 1e-16f);
    float inv1 = 1.f / (sum1 + 1e-16f);
    for (int i = lane; i <= cnt; i += 32) {
        int s = (i < cnt) ? g_esrc[o + i] : n;
        float a0 = expf(lrelu(g_al1[s * 4 + 0] + dd0) - m0) * inv0;
        float a1 = expf(lrelu(g_al1[s * 4 + 1] + dd1) - m1) * inv1;
        if (i < cnt) {
            g_alpha1[(size_t)(o + i) * 2 + 0] = a0;
            g_alpha1[(size_t)(o + i) * 2 + 1] = a1;
        } else {
            g_salpha1[n * 2 + 0] = a0;
            g_salpha1[n * 2 + 1] = a1;
        }
    }
}

__global__ void alpha2_kernel() {
    int n = (blockIdx.x * blockDim.x + threadIdx.x) >> 5;
    if (n >= NN) return;
    int lane = threadIdx.x & 31;
    int o = g_off[n];
    int cnt = g_off[n + 1] - o;
    float dd = g_al2[n * 2 + 1];

    float m = -1e30f;
    for (int i = lane; i <= cnt; i += 32) {
        int s = (i < cnt) ? g_esrc[o + i] : n;
        m = fmaxf(m, lrelu(g_al2[s * 2] + dd));
    }
    #pragma unroll
    for (int x = 16; x; x >>= 1)
        m = fmaxf(m, __shfl_xor_sync(0xffffffffu, m, x));
    float sum = 0.f;
    for (int i = lane; i <= cnt; i += 32) {
        int s = (i < cnt) ? g_esrc[o + i] : n;
        sum += expf(lrelu(g_al2[s * 2] + dd) - m);
    }
    #pragma unroll
    for (int x = 16; x; x >>= 1)
        sum += __shfl_xor_sync(0xffffffffu, sum, x);
    float inv = 1.f / (sum + 1e-16f);
    for (int i = lane; i <= cnt; i += 32) {
        int s = (i < cnt) ? g_esrc[o + i] : n;
        float a = expf(lrelu(g_al2[s * 2] + dd) - m) * inv;
        if (i < cnt) g_alpha2[o + i] = a;
        else g_salpha2[n] = a;
    }
}

// ---------------- aggregation ----------------
__global__ __launch_bounds__(128) void agg1_kernel(const float* __restrict__ b1) {
    int n = blockIdx.x;
    int tid = threadIdx.x;
    int o = g_off[n];
    int cnt = g_off[n + 1] - o;
    int head = tid >> 6;

    __shared__ int   ssrc[128];
    __shared__ float sal[128 * 2];

    float4 acc = make_float4(0.f, 0.f, 0.f, 0.f);
    for (int base = 0; base < cnt; base += 128) {
        int m = min(128, cnt - base);
        if (tid < m) {
            ssrc[tid] = g_esrc[o + base + tid];
            sal[tid * 2 + 0] = g_alpha1[(size_t)(o + base + tid) * 2 + 0];
            sal[tid * 2 + 1] = g_alpha1[(size_t)(o + base + tid) * 2 + 1];
        }
        __syncthreads();
        for (int j = 0; j < m; j++) {
            float a = sal[j * 2 + head];
            const float4* r = (const float4*)(g_g1 + (size_t)ssrc[j] * DD);
            float4 v = r[tid];
            acc.x = fmaf(a, v.x, acc.x);
            acc.y = fmaf(a, v.y, acc.y);
            acc.z = fmaf(a, v.z, acc.z);
            acc.w = fmaf(a, v.w, acc.w);
        }
        __syncthreads();
    }
    {
        float a = g_salpha1[n * 2 + head];
        float4 v = ((const float4*)(g_g1 + (size_t)n * DD))[tid];
        acc.x = fmaf(a, v.x, acc.x);
        acc.y = fmaf(a, v.y, acc.y);
        acc.z = fmaf(a, v.z, acc.z);
        acc.w = fmaf(a, v.w, acc.w);
    }
    float4 bb = ((const float4*)b1)[tid];
    acc.x = fmaxf(acc.x + bb.x, 0.f);
    acc.y = fmaxf(acc.y + bb.y, 0.f);
    acc.z = fmaxf(acc.z + bb.z, 0.f);
    acc.w = fmaxf(acc.w + bb.w, 0.f);
    uint4 w;
    split_pack(acc.x, acc.y, w.x, w.y);
    split_pack(acc.z, acc.w, w.z, w.w);
    *(uint4*)(g_h1p + (size_t)n * DD + 4 * tid) = w;
}

__global__ __launch_bounds__(128) void agg2_kernel(const float* __restrict__ b2,
                                                   float* __restrict__ out) {
    int n = blockIdx.x;
    int tid = threadIdx.x;
    int o = g_off[n];
    int cnt = g_off[n + 1] - o;

    __shared__ int   ssrc[128];
    __shared__ float sal[128];

    float4 acc = make_float4(0.f, 0.f, 0.f, 0.f);
    for (int base = 0; base < cnt; base += 128) {
        int m = min(128, cnt - base);
        if (tid < m) {
            ssrc[tid] = g_esrc[o + base + tid];
            sal[tid] = g_alpha2[o + base + tid];
        }
        __syncthreads();
        for (int j = 0; j < m; j++) {
            float a = sal[j];
            const float4* r = (const float4*)(g_g2 + (size_t)ssrc[j] * DD);
            float4 v = r[tid];
            acc.x = fmaf(a, v.x, acc.x);
            acc.y = fmaf(a, v.y, acc.y);
            acc.z = fmaf(a, v.z, acc.z);
            acc.w = fmaf(a, v.w, acc.w);
        }
        __syncthreads();
    }
    {
        float a = g_salpha2[n];
        float4 v = ((const float4*)(g_g2 + (size_t)n * DD))[tid];
        acc.x = fmaf(a, v.x, acc.x);
        acc.y = fmaf(a, v.y, acc.y);
        acc.z = fmaf(a, v.z, acc.z);
        acc.w = fmaf(a, v.w, acc.w);
    }
    float4 bb = ((const float4*)b2)[tid];
    acc.x = fmaxf(acc.x + bb.x, 0.f);
    acc.y = fmaxf(acc.y + bb.y, 0.f);
    acc.z = fmaxf(acc.z + bb.z, 0.f);
    acc.w = fmaxf(acc.w + bb.w, 0.f);
    ((float4*)(out + (size_t)n * DD))[tid] = acc;
}

// ---------------- launcher ----------------
template <typename T>
static T* sym_p(const void* sym) {
    void* p = nullptr;
    cudaGetSymbolAddress(&p, sym);
    return (T*)p;
}

extern "C" void kernel_launch(void* const* d_in, const int* in_sizes, int n_in,
                              void* d_out, int out_size) {
    const float* x      = (const float*)d_in[0];
    const int*   adj    = (const int*)d_in[1];
    const float* W_fc   = (const float*)d_in[2];
    const float* b_fc   = (const float*)d_in[3];
    const float* W1     = (const float*)d_in[4];
    const float* a1_src = (const float*)d_in[5];
    const float* a1_dst = (const float*)d_in[6];
    const float* b1     = (const float*)d_in[7];
    const float* W2     = (const float*)d_in[8];
    const float* a2_src = (const float*)d_in[9];
    const float* a2_dst = (const float*)d_in[10];
    const float* b2     = (const float*)d_in[11];
    float* out = (float*)d_out;

    uint32_t* p_xp  = sym_p<uint32_t>(g_xp);
    uint32_t* p_h0p = sym_p<uint32_t>(g_h0p);
    uint32_t* p_h1p = sym_p<uint32_t>(g_h1p);
    float*    p_g1  = sym_p<float>(g_g1);
    float*    p_g2  = sym_p<float>(g_g2);
    uint4*    p_wfc = sym_p<uint4>(g_wfcp);
    uint4*    p_w1  = sym_p<uint4>(g_w1p);
    uint4*    p_w2  = sym_p<uint4>(g_w2p);

    const int dyn = NSTG * STG_BYTES;   // 64 KB
    cudaFuncSetAttribute(tgemm_p_kernel<0>,
                         cudaFuncAttributeMaxDynamicSharedMemorySize, dyn);
    cudaFuncSetAttribute(tgemm_p_kernel<1>,
                         cudaFuncAttributeMaxDynamicSharedMemorySize, dyn);

    // ---- fork: side branch — projections, W2 pack, CSR build
    cudaEventRecord(g_evF, 0);
    cudaStreamWaitEvent(g_side, g_evF, 0);
    proj1_kernel<<<(H1C * 32 + 255) / 256, 256, 0, g_side>>>(W1, a1_src, a1_dst);
    proj2_kernel<<<(DD * 32 + 255) / 256, 256, 0, g_side>>>(W2, a2_src, a2_dst);
    pack_b_kernel<<<((DD / 4) * DD + 255) / 256, 256, 0, g_side>>>(W2, p_w2, DD, DD);
    zero_kernel<<<(NN + 255) / 256, 256, 0, g_side>>>();
    count_kernel<<<(EE + 255) / 256, 256, 0, g_side>>>(adj);
    scan_kernel<<<1, 256, 0, g_side>>>();
    scatter_kernel<<<(EE + 255) / 256, 256, 0, g_side>>>(adj);

    // ---- main branch
    pack_a_kernel<<<(NN * H1C / 2 + 255) / 256, 256>>>(x, p_xp, NN * H1C / 2);
    pack_b_kernel<<<((H1C / 4) * H1C + 255) / 256, 256>>>(W_fc, p_wfc, H1C, H1C);
    pack_b_kernel<<<((H1C / 4) * DD + 255) / 256, 256>>>(W1, p_w1, H1C, DD);

    // fc + relu -> packed h0
    {
        dim3 grid(H1C / 128, NN / 128);
        tgemm_p_kernel<1><<<grid, 256, dyn>>>(p_xp, p_wfc, b_fc, p_h0p, NN, H1C, H1C);
    }
    cudaEventRecord(g_evG1, 0);

    // side: al1 + alpha1 run concurrently with main's GEMM2
    cudaStreamWaitEvent(g_side, g_evG1, 0);
    al1p_kernel<<<(NN * 32 + 255) / 256, 256, 0, g_side>>>();
    alpha1_kernel<<<(NN * 32 + 255) / 256, 256, 0, g_side>>>();
    cudaEventRecord(g_evJ1, g_side);

    // main: g1 = h0 @ W1 (fp32)
    {
        dim3 grid(DD / 128, NN / 128);
        tgemm_p_kernel<0><<<grid, 256, dyn>>>(p_h0p, p_w1, nullptr, p_g1, NN, DD, H1C);
    }

    // join 1: alpha1 ready -> agg1
    cudaStreamWaitEvent(0, g_evJ1, 0);
    agg1_kernel<<<NN, 128>>>(b1);          // -> packed h1
    cudaEventRecord(g_evA1, 0);

    // side: al2 + alpha2 run concurrently with main's GEMM3
    cudaStreamWaitEvent(g_side, g_evA1, 0);
    al2p_kernel<<<(NN * 32 + 255) / 256, 256, 0, g_side>>>();
    alpha2_kernel<<<(NN * 32 + 255) / 256, 256, 0, g_side>>>();
    cudaEventRecord(g_evJ2, g_side);

    // main: g2 = h1 @ W2 (fp32)
    {
        dim3 grid(DD / 128, NN / 128);
        tgemm_p_kernel<0><<<grid, 256, dyn>>>(p_h1p, p_w2, nullptr, p_g2, NN, DD, DD);
    }

    // join 2: alpha2 ready -> agg2
    cudaStreamWaitEvent(0, g_evJ2, 0);
    agg2_kernel<<<NN, 128>>>(b2, out);
}

// round 14
// speedup vs baseline: 1.2790x; 1.0136x over previous
#include <cuda_runtime.h>
#include <cuda_bf16.h>
#include <cstdint>

#define NN 16384
#define EE 262144
#define H1C 256
#define DD 512
#define NEG_SLOPE 0.2f

// ---------------- device scratch ----------------
__device__ uint32_t g_xp [NN * H1C];
__device__ uint32_t g_h0p[NN * H1C];
__device__ uint32_t g_h1p[(size_t)NN * DD];
__device__ float    g_g1[(size_t)NN * DD];
__device__ float    g_g2[(size_t)NN * DD];
__device__ uint4 g_wfcp[(H1C / 4) * H1C];
__device__ uint4 g_w1p [(H1C / 4) * DD];
__device__ uint4 g_w2p [(DD / 4) * DD];
__device__ float4 g_P1[H1C];
__device__ float2 g_P2[DD];

__device__ float g_al1[NN * 4];
__device__ float g_al2[NN * 2];
__device__ __align__(16) int g_deg[NN];
__device__ int   g_cursor[NN];
__device__ __align__(16) int g_off[NN + 1];
__device__ int   g_esrc[EE];
__device__ float g_alpha1[(size_t)EE * 2];
__device__ float g_salpha1[NN * 2];
__device__ float g_alpha2[EE];
__device__ float g_salpha2[NN];

// ---------------- streams / events ----------------
static cudaStream_t g_side = nullptr;
static cudaEvent_t g_evF, g_evG1, g_evJ1, g_evG2a, g_evH0, g_evA1, g_evG3a, g_evJ2, g_evH2;
namespace {
struct StreamInit {
    StreamInit() {
        cudaStreamCreateWithFlags(&g_side, cudaStreamNonBlocking);
        cudaEventCreateWithFlags(&g_evF,  cudaEventDisableTiming);
        cudaEventCreateWithFlags(&g_evG1, cudaEventDisableTiming);
        cudaEventCreateWithFlags(&g_evJ1, cudaEventDisableTiming);
        cudaEventCreateWithFlags(&g_evG2a, cudaEventDisableTiming);
        cudaEventCreateWithFlags(&g_evH0, cudaEventDisableTiming);
        cudaEventCreateWithFlags(&g_evA1, cudaEventDisableTiming);
        cudaEventCreateWithFlags(&g_evG3a, cudaEventDisableTiming);
        cudaEventCreateWithFlags(&g_evJ2, cudaEventDisableTiming);
        cudaEventCreateWithFlags(&g_evH2, cudaEventDisableTiming);
    }
};
static StreamInit g_si;
}

// ---------------- split helpers ----------------
__device__ __forceinline__ void split_pack(float x0, float x1,
                                           uint32_t& hi, uint32_t& lo) {
    __nv_bfloat16 h0 = __float2bfloat16_rn(x0);
    __nv_bfloat16 h1 = __float2bfloat16_rn(x1);
    hi = (uint32_t)__bfloat16_as_ushort(h0) |
         ((uint32_t)__bfloat16_as_ushort(h1) << 16);
    float l0 = x0 - __bfloat162float(h0);
    float l1 = x1 - __bfloat162float(h1);
    __nv_bfloat162 lp = __floats2bfloat162_rn(l0, l1);
    lo = *reinterpret_cast<const uint32_t*>(&lp);
}
__device__ __forceinline__ float bf_lo(uint32_t w) {
    return __bfloat162float(__ushort_as_bfloat16((unsigned short)(w & 0xffffu)));
}
__device__ __forceinline__ float bf_hi(uint32_t w) {
    return __bfloat162float(__ushort_as_bfloat16((unsigned short)(w >> 16)));
}

// ---------------- pack kernels ----------------
__global__ void pack_a_kernel(const float* __restrict__ X,
                              uint32_t* __restrict__ P, int npairs) {
    int i = blockIdx.x * blockDim.x + threadIdx.x;
    if (i < npairs) {
        float2 v = *(const float2*)(X + 2 * (size_t)i);
        split_pack(v.x, v.y, P[2 * (size_t)i], P[2 * (size_t)i + 1]);
    }
}
__global__ void pack_b_kernel(const float* __restrict__ W,
                              uint4* __restrict__ P, int K, int N) {
    int idx = blockIdx.x * blockDim.x + threadIdx.x;
    int total = (K / 4) * N;
    if (idx >= total) return;
    int c = idx / N;
    int n = idx - c * N;
    const float* wp = W + (size_t)(4 * c) * N + n;
    uint4 o;
    split_pack(wp[0], wp[N], o.x, o.y);
    split_pack(wp[2 * N], wp[3 * N], o.z, o.w);
    P[idx] = o;
}

// ---------------- projection kernels ----------------
__global__ void proj1_kernel(const float* __restrict__ W1,
                             const float* __restrict__ a1s,
                             const float* __restrict__ a1d) {
    int k = (blockIdx.x * blockDim.x + threadIdx.x) >> 5;
    if (k >= H1C) return;
    int lane = threadIdx.x & 31;
    const float* wr = W1 + (size_t)k * DD;
    float s0 = 0.f, s1 = 0.f, d0 = 0.f, d1 = 0.f;
    for (int c = lane; c < H1C; c += 32) {
        float w0 = wr[c];
        float w1 = wr[H1C + c];
        s0 = fmaf(w0, a1s[c], s0);
        s1 = fmaf(w1, a1s[H1C + c], s1);
        d0 = fmaf(w0, a1d[c], d0);
        d1 = fmaf(w1, a1d[H1C + c], d1);
    }
    #pragma unroll
    for (int o = 16; o; o >>= 1) {
        s0 += __shfl_down_sync(0xffffffffu, s0, o);
        s1 += __shfl_down_sync(0xffffffffu, s1, o);
        d0 += __shfl_down_sync(0xffffffffu, d0, o);
        d1 += __shfl_down_sync(0xffffffffu, d1, o);
    }
    if (lane == 0) g_P1[k] = make_float4(s0, s1, d0, d1);
}
__global__ void proj2_kernel(const float* __restrict__ W2,
                             const float* __restrict__ a2s,
                             const float* __restrict__ a2d) {
    int k = (blockIdx.x * blockDim.x + threadIdx.x) >> 5;
    if (k >= DD) return;
    int lane = threadIdx.x & 31;
    const float* wr = W2 + (size_t)k * DD;
    float s = 0.f, d = 0.f;
    for (int c = lane; c < DD; c += 32) {
        float w = wr[c];
        s = fmaf(w, a2s[c], s);
        d = fmaf(w, a2d[c], d);
    }
    #pragma unroll
    for (int o = 16; o; o >>= 1) {
        s += __shfl_down_sync(0xffffffffu, s, o);
        d += __shfl_down_sync(0xffffffffu, d, o);
    }
    if (lane == 0) g_P2[k] = make_float2(s, d);
}

// ---------------- CSR ----------------
__global__ void zero_kernel() {
    int i = blockIdx.x * blockDim.x + threadIdx.x;
    if (i < NN) { g_deg[i] = 0; g_cursor[i] = 0; }
}
__global__ void count_kernel(const int* __restrict__ adj) {
    int i = blockIdx.x * blockDim.x + threadIdx.x;
    if (i < EE) atomicAdd(&g_deg[adj[EE + i]], 1);
}
__global__ void scan_kernel() {
    int t = threadIdx.x;
    int4 v[16];
    const int4* dp = (const int4*)g_deg + t * 16;
    #pragma unroll
    for (int k = 0; k < 16; k++) v[k] = dp[k];
    int sum = 0;
    #pragma unroll
    for (int k = 0; k < 16; k++) sum += v[k].x + v[k].y + v[k].z + v[k].w;
    __shared__ int part[256];
    part[t] = sum;
    __syncthreads();
    for (int s = 1; s < 256; s <<= 1) {
        int q = (t >= s) ? part[t - s] : 0;
        __syncthreads();
        part[t] += q;
        __syncthreads();
    }
    int run = (t > 0) ? part[t - 1] : 0;
    int4* op = (int4*)g_off + t * 16;
    #pragma unroll
    for (int k = 0; k < 16; k++) {
        int4 o;
        o.x = run; run += v[k].x;
        o.y = run; run += v[k].y;
        o.z = run; run += v[k].z;
        o.w = run; run += v[k].w;
        op[k] = o;
    }
    if (t == 255) g_off[NN] = run;
}
__global__ void scatter_kernel(const int* __restrict__ adj) {
    int i = blockIdx.x * blockDim.x + threadIdx.x;
    if (i < EE) {
        int src = adj[i];
        int dst = adj[EE + i];
        int p = g_off[dst] + atomicAdd(&g_cursor[dst], 1);
        g_esrc[p] = src;
    }
}

// ================= Tensor-core GEMM (bf16x3, cp.async pipeline) =================
__device__ __forceinline__ int smw(int outer, int kw) {
    int line = outer >> 1;
    int M = ((line & 3) << 1) | ((line >> 2) & 1);
    int lc = ((outer & 1) << 2) + (kw >> 1);
    return line * 32 + (((lc ^ M) << 2) | ((kw & 1) << 1));
}
__device__ __forceinline__ void mma16816(float* d, const uint32_t* a,
                                         const uint32_t* b) {
    asm volatile(
        "mma.sync.aligned.m16n8k16.row.col.f32.bf16.bf16.f32 "
        "{%0,%1,%2,%3}, {%4,%5,%6,%7}, {%8,%9}, {%0,%1,%2,%3};\n"
        : "+f"(d[0]), "+f"(d[1]), "+f"(d[2]), "+f"(d[3])
        : "r"(a[0]), "r"(a[1]), "r"(a[2]), "r"(a[3]),
          "r"(b[0]), "r"(b[1]));
}
__device__ __forceinline__ uint32_t smem_u32(const void* p) {
    uint32_t a;
    asm("{ .reg .u64 t; cvta.to.shared.u64 t, %1; cvt.u32.u64 %0, t; }"
        : "=r"(a) : "l"(p));
    return a;
}
__device__ __forceinline__ void cp16(uint32_t dst, const void* src) {
    asm volatile("cp.async.cg.shared.global [%0], [%1], 16;"
                 :: "r"(dst), "l"(src));
}
#define CP_COMMIT() asm volatile("cp.async.commit_group;" ::: "memory")
#define STG_BYTES 16384
#define NSTG 4

__device__ __forceinline__ void fill_stage(
    const uint32_t* __restrict__ Ap, const uint4* __restrict__ Bp,
    int brow, int bcol, int K, int N, int k0, int tid, uint32_t sbase)
{
    int c4 = tid & 3;
    #pragma unroll
    for (int f = 0; f < 2; f++) {
        int row = (tid >> 2) + 64 * f;
        cp16(sbase + 4 * smw(row, 2 * c4),
             Ap + (size_t)(brow + row) * K + k0 + 4 * c4);
    }
    int tc = tid >> 6;
    int m  = tid & 63;
    const uint4* bp = Bp + (size_t)((k0 >> 2) + tc) * N + bcol + 2 * m;
    uint32_t bB = sbase + 8192;
    cp16(bB + 4 * smw(2 * m,     2 * tc), bp);
    cp16(bB + 4 * smw(2 * m + 1, 2 * tc), bp + 1);
}

// OUT_MODE: 0 = fp32 plain, 1 = packed split-bf16 with bias+relu
// N is the row stride of B/C; column extent = gridDim.x*128 (callers pre-offset).
template <int OUT_MODE>
__global__ __launch_bounds__(256, 2) void tgemm_p_kernel(
    const uint32_t* __restrict__ Ap, const uint4* __restrict__ Bp,
    const float* __restrict__ bias, void* __restrict__ Cout,
    int M, int N, int K)
{
    extern __shared__ uint32_t dynsm[];
    const uint32_t sb = smem_u32(dynsm);

    const int tid  = threadIdx.x;
    const int lane = tid & 31;
    const int wid  = tid >> 5;
    const int wm   = wid & 1;
    const int wn   = wid >> 1;
    const int brow = blockIdx.y * 128;
    const int bcol = blockIdx.x * 128;

    float acc[4][4][4];
    #pragma unroll
    for (int i = 0; i < 4; i++)
        #pragma unroll
        for (int j = 0; j < 4; j++)
            #pragma unroll
            for (int q = 0; q < 4; q++) acc[i][j][q] = 0.f;

    const int iters = K >> 4;

    #pragma unroll
    for (int s = 0; s < NSTG - 1; s++) {
        if (s < iters) {
            fill_stage(Ap, Bp, brow, bcol, K, N, s << 4, tid, sb + s * STG_BYTES);
            CP_COMMIT();
        }
    }

    const int c  = lane & 3;
    const int r4 = lane >> 2;
    const int offA0 = smw(r4, c);
    const int offA1 = smw(8 + r4, c);
    const int offA2 = smw(r4, c + 4);
    const int offA3 = smw(8 + r4, c + 4);

    for (int it = 0; it < iters; ++it) {
        int rem = iters - 1 - it;
        if (rem >= 2)      asm volatile("cp.async.wait_group 2;" ::: "memory");
        else if (rem == 1) asm volatile("cp.async.wait_group 1;" ::: "memory");
        else               asm volatile("cp.async.wait_group 0;" ::: "memory");
        __syncthreads();

        uint32_t* buf  = dynsm + (it & (NSTG - 1)) * 4096;
        uint32_t* Abuf = buf;
        uint32_t* Bbuf = buf + 2048;

        uint2 bfr[4][2];
        #pragma unroll
        for (int ni = 0; ni < 4; ni++) {
            int base = wn * 512;
            bfr[ni][0] = *(const uint2*)&Bbuf[base + smw(ni * 8 + r4, c)];
            bfr[ni][1] = *(const uint2*)&Bbuf[base + smw(ni * 8 + r4, c + 4)];
        }
        #pragma unroll
        for (int mi = 0; mi < 4; mi++) {
            int base = (wm * 64 + mi * 16) * 16;
            uint2 a0 = *(const uint2*)&Abuf[base + offA0];
            uint2 a1 = *(const uint2*)&Abuf[base + offA1];
            uint2 a2 = *(const uint2*)&Abuf[base + offA2];
            uint2 a3 = *(const uint2*)&Abuf[base + offA3];
            uint32_t ah[4] = {a0.x, a1.x, a2.x, a3.x};
            uint32_t al[4] = {a0.y, a1.y, a2.y, a3.y};
            #pragma unroll
            for (int ni = 0; ni < 4; ni++) {
                uint32_t bh[2] = {bfr[ni][0].x, bfr[ni][1].x};
                uint32_t bl[2] = {bfr[ni][0].y, bfr[ni][1].y};
                mma16816(acc[mi][ni], ah, bh);
                mma16816(acc[mi][ni], ah, bl);
                mma16816(acc[mi][ni], al, bh);
            }
        }

        if (it + NSTG - 1 < iters) {
            fill_stage(Ap, Bp, brow, bcol, K, N, (it + NSTG - 1) << 4, tid,
                       sb + ((it + NSTG - 1) & (NSTG - 1)) * STG_BYTES);
            CP_COMMIT();
        }
    }

    #pragma unroll
    for (int mi = 0; mi < 4; mi++) {
        int row = brow + wm * 64 + mi * 16 + r4;
        #pragma unroll
        for (int ni = 0; ni < 4; ni++) {
            int col = bcol + wn * 32 + ni * 8 + 2 * c;
            float2 v0 = make_float2(acc[mi][ni][0], acc[mi][ni][1]);
            float2 v1 = make_float2(acc[mi][ni][2], acc[mi][ni][3]);
            if (OUT_MODE == 1) {
                float2 bb = *(const float2*)(bias + col);
                v0.x = fmaxf(v0.x + bb.x, 0.f); v0.y = fmaxf(v0.y + bb.y, 0.f);
                v1.x = fmaxf(v1.x + bb.x, 0.f); v1.y = fmaxf(v1.y + bb.y, 0.f);
                uint2 w0, w1;
                split_pack(v0.x, v0.y, w0.x, w0.y);
                split_pack(v1.x, v1.y, w1.x, w1.y);
                uint32_t* P = (uint32_t*)Cout;
                *(uint2*)(P + (size_t)row * N + col)       = w0;
                *(uint2*)(P + (size_t)(row + 8) * N + col) = w1;
            } else {
                float* C = (float*)Cout;
                *(float2*)(C + (size_t)row * N + col)       = v0;
                *(float2*)(C + (size_t)(row + 8) * N + col) = v1;
            }
        }
    }
}

// ---------------- attention scalars from packed h via projections ----------------
__global__ void al1p_kernel() {
    int n = (blockIdx.x * blockDim.x + threadIdx.x) >> 5;
    if (n >= NN) return;
    int lane = threadIdx.x & 31;
    const uint2* row = (const uint2*)(g_h0p + (size_t)n * H1C);
    float s0 = 0.f, s1 = 0.f, d0 = 0.f, d1 = 0.f;
    for (int i = lane; i < 128; i += 32) {
        uint2 w = row[i];
        float x0 = bf_lo(w.x) + bf_lo(w.y);
        float x1 = bf_hi(w.x) + bf_hi(w.y);
        float4 p0 = g_P1[2 * i];
        float4 p1 = g_P1[2 * i + 1];
        s0 += x0 * p0.x + x1 * p1.x;
        s1 += x0 * p0.y + x1 * p1.y;
        d0 += x0 * p0.z + x1 * p1.z;
        d1 += x0 * p0.w + x1 * p1.w;
    }
    #pragma unroll
    for (int o = 16; o; o >>= 1) {
        s0 += __shfl_down_sync(0xffffffffu, s0, o);
        s1 += __shfl_down_sync(0xffffffffu, s1, o);
        d0 += __shfl_down_sync(0xffffffffu, d0, o);
        d1 += __shfl_down_sync(0xffffffffu, d1, o);
    }
    if (lane == 0) ((float4*)g_al1)[n] = make_float4(s0, s1, d0, d1);
}

__global__ void al2p_kernel() {
    int n = (blockIdx.x * blockDim.x + threadIdx.x) >> 5;
    if (n >= NN) return;
    int lane = threadIdx.x & 31;
    const uint2* row = (const uint2*)(g_h1p + (size_t)n * DD);
    float s = 0.f, d = 0.f;
    for (int i = lane; i < 256; i += 32) {
        uint2 w = row[i];
        float x0 = bf_lo(w.x) + bf_lo(w.y);
        float x1 = bf_hi(w.x) + bf_hi(w.y);
        float2 p0 = g_P2[2 * i];
        float2 p1 = g_P2[2 * i + 1];
        s += x0 * p0.x + x1 * p1.x;
        d += x0 * p0.y + x1 * p1.y;
    }
    #pragma unroll
    for (int o = 16; o; o >>= 1) {
        s += __shfl_down_sync(0xffffffffu, s, o);
        d += __shfl_down_sync(0xffffffffu, d, o);
    }
    if (lane == 0) ((float2*)g_al2)[n] = make_float2(s, d);
}

__device__ __forceinline__ float lrelu(float x) {
    return x > 0.f ? x : NEG_SLOPE * x;
}

// ---------------- edge softmax ----------------
__global__ void alpha1_kernel() {
    int n = (blockIdx.x * blockDim.x + threadIdx.x) >> 5;
    if (n >= NN) return;
    int lane = threadIdx.x & 31;
    int o = g_off[n];
    int cnt = g_off[n + 1] - o;
    float dd0 = g_al1[n * 4 + 2];
    float dd1 = g_al1[n * 4 + 3];

    float m0 = -1e30f, m1 = -1e30f;
    for (int i = lane; i <= cnt; i += 32) {
        int s = (i < cnt) ? g_esrc[o + i] : n;
        m0 = fmaxf(m0, lrelu(g_al1[s * 4 + 0] + dd0));
        m1 = fmaxf(m1, lrelu(g_al1[s * 4 + 1] + dd1));
    }
    #pragma unroll
    for (int x = 16; x; x >>= 1) {
        m0 = fmaxf(m0, __shfl_xor_sync(0xffffffffu, m0, x));
        m1 = fmaxf(m1, __shfl_xor_sync(0xffffffffu, m1, x));
    }
    float sum0 = 0.f, sum1 = 0.f;
    for (int i = lane; i <= cnt; i += 32) {
        int s = (i < cnt) ? g_esrc[o + i] : n;
        sum0 += expf(lrelu(g_al1[s * 4 + 0] + dd0) - m0);
        sum1 += expf(lrelu(g_al1[s * 4 + 1] + dd1) - m1);
    }
    #pragma unroll
    for (int x = 16; x; x >>= 1) {
        sum0 += __shfl_xor_sync(0xffffffffu, sum0, x);
        sum1 += __shfl_xor_sync(0xffffffffu, sum1, x);
    }
    float inv0 = 1.f / (sum0 + 1e-16f);
    float inv1 = 1.f / (sum1 + 1e-16f);
    for (int i = lane; i <= cnt; i += 32) {
        int s = (i < cnt) ? g_esrc[o + i] : n;
        float a0 = expf(lrelu(g_al1[s * 4 + 0] + dd0) - m0) * inv0;
        float a1 = expf(lrelu(g_al1[s * 4 + 1] + dd1) - m1) * inv1;
        if (i < cnt) {
            g_alpha1[(size_t)(o + i) * 2 + 0] = a0;
            g_alpha1[(size_t)(o + i) * 2 + 1] = a1;
        } else {
            g_salpha1[n * 2 + 0] = a0;
            g_salpha1[n * 2 + 1] = a1;
        }
    }
}

__global__ void alpha2_kernel() {
    int n = (blockIdx.x * blockDim.x + threadIdx.x) >> 5;
    if (n >= NN) return;
    int lane = threadIdx.x & 31;
    int o = g_off[n];
    int cnt = g_off[n + 1] - o;
    float dd = g_al2[n * 2 + 1];

    float m = -1e30f;
    for (int i = lane; i <= cnt; i += 32) {
        int s = (i < cnt) ? g_esrc[o + i] : n;
        m = fmaxf(m, lrelu(g_al2[s * 2] + dd));
    }
    #pragma unroll
    for (int x = 16; x; x >>= 1)
        m = fmaxf(m, __shfl_xor_sync(0xffffffffu, m, x));
    float sum = 0.f;
    for (int i = lane; i <= cnt; i += 32) {
        int s = (i < cnt) ? g_esrc[o + i] : n;
        sum += expf(lrelu(g_al2[s * 2] + dd) - m);
    }
    #pragma unroll
    for (int x = 16; x; x >>= 1)
        sum += __shfl_xor_sync(0xffffffffu, sum, x);
    float inv = 1.f / (sum + 1e-16f);
    for (int i = lane; i <= cnt; i += 32) {
        int s = (i < cnt) ? g_esrc[o + i] : n;
        float a = expf(lrelu(g_al2[s * 2] + dd) - m) * inv;
        if (i < cnt) g_alpha2[o + i] = a;
        else g_salpha2[n] = a;
    }
}

// ---------------- aggregation halves ----------------
__global__ __launch_bounds__(64) void agg1h_kernel(const float* __restrict__ b1,
                                                   int head) {
    int n = blockIdx.x;
    int tid = threadIdx.x;
    int o = g_off[n];
    int cnt = g_off[n + 1] - o;

    __shared__ int   ssrc[64];
    __shared__ float sal[64];

    const float* gbase = g_g1 + (size_t)head * H1C;
    float4 acc = make_float4(0.f, 0.f, 0.f, 0.f);
    for (int base = 0; base < cnt; base += 64) {
        int m = min(64, cnt - base);
        if (tid < m) {
            int e = o + base + tid;
            ssrc[tid] = g_esrc[e];
            sal[tid] = g_alpha1[(size_t)e * 2 + head];
        }
        __syncthreads();
        for (int j = 0; j < m; j++) {
            float a = sal[j];
            float4 v = ((const float4*)(gbase + (size_t)ssrc[j] * DD))[tid];
            acc.x = fmaf(a, v.x, acc.x);
            acc.y = fmaf(a, v.y, acc.y);
            acc.z = fmaf(a, v.z, acc.z);
            acc.w = fmaf(a, v.w, acc.w);
        }
        __syncthreads();
    }
    {
        float a = g_salpha1[n * 2 + head];
        float4 v = ((const float4*)(gbase + (size_t)n * DD))[tid];
        acc.x = fmaf(a, v.x, acc.x);
        acc.y = fmaf(a, v.y, acc.y);
        acc.z = fmaf(a, v.z, acc.z);
        acc.w = fmaf(a, v.w, acc.w);
    }
    float4 bb = ((const float4*)(b1 + head * H1C))[tid];
    acc.x = fmaxf(acc.x + bb.x, 0.f);
    acc.y = fmaxf(acc.y + bb.y, 0.f);
    acc.z = fmaxf(acc.z + bb.z, 0.f);
    acc.w = fmaxf(acc.w + bb.w, 0.f);
    uint4 w;
    split_pack(acc.x, acc.y, w.x, w.y);
    split_pack(acc.z, acc.w, w.z, w.w);
    *(uint4*)(g_h1p + (size_t)n * DD + head * H1C + 4 * tid) = w;
}

__global__ __launch_bounds__(64) void agg2h_kernel(const float* __restrict__ b2,
                                                   float* __restrict__ out,
                                                   int half) {
    int n = blockIdx.x;
    int tid = threadIdx.x;
    int o = g_off[n];
    int cnt = g_off[n + 1] - o;

    __shared__ int   ssrc[64];
    __shared__ float sal[64];

    const float* gbase = g_g2 + (size_t)half * H1C;
    float4 acc = make_float4(0.f, 0.f, 0.f, 0.f);
    for (int base = 0; base < cnt; base += 64) {
        int m = min(64, cnt - base);
        if (tid < m) {
            ssrc[tid] = g_esrc[o + base + tid];
            sal[tid] = g_alpha2[o + base + tid];
        }
        __syncthreads();
        for (int j = 0; j < m; j++) {
            float a = sal[j];
            float4 v = ((const float4*)(gbase + (size_t)ssrc[j] * DD))[tid];
            acc.x = fmaf(a, v.x, acc.x);
            acc.y = fmaf(a, v.y, acc.y);
            acc.z = fmaf(a, v.z, acc.z);
            acc.w = fmaf(a, v.w, acc.w);
        }
        __syncthreads();
    }
    {
        float a = g_salpha2[n];
        float4 v = ((const float4*)(gbase + (size_t)n * DD))[tid];
        acc.x = fmaf(a, v.x, acc.x);
        acc.y = fmaf(a, v.y, acc.y);
        acc.z = fmaf(a, v.z, acc.z);
        acc.w = fmaf(a, v.w, acc.w);
    }
    float4 bb = ((const float4*)(b2 + half * H1C))[tid];
    acc.x = fmaxf(acc.x + bb.x, 0.f);
    acc.y = fmaxf(acc.y + bb.y, 0.f);
    acc.z = fmaxf(acc.z + bb.z, 0.f);
    acc.w = fmaxf(acc.w + bb.w, 0.f);
    *(float4*)(out + (size_t)n * DD + half * H1C + 4 * tid) = acc;
}

// no-op kernel for clean stream join as last graph node
__global__ void join_kernel() {}

// ---------------- launcher ----------------
template <typename T>
static T* sym_p(const void* sym) {
    void* p = nullptr;
    cudaGetSymbolAddress(&p, sym);
    return (T*)p;
}

extern "C" void kernel_launch(void* const* d_in, const int* in_sizes, int n_in,
                              void* d_out, int out_size) {
    const float* x      = (const float*)d_in[0];
    const int*   adj    = (const int*)d_in[1];
    const float* W_fc   = (const float*)d_in[2];
    const float* b_fc   = (const float*)d_in[3];
    const float* W1     = (const float*)d_in[4];
    const float* a1_src = (const float*)d_in[5];
    const float* a1_dst = (const float*)d_in[6];
    const float* b1     = (const float*)d_in[7];
    const float* W2     = (const float*)d_in[8];
    const float* a2_src = (const float*)d_in[9];
    const float* a2_dst = (const float*)d_in[10];
    const float* b2     = (const float*)d_in[11];
    float* out = (float*)d_out;

    uint32_t* p_xp  = sym_p<uint32_t>(g_xp);
    uint32_t* p_h0p = sym_p<uint32_t>(g_h0p);
    uint32_t* p_h1p = sym_p<uint32_t>(g_h1p);
    float*    p_g1  = sym_p<float>(g_g1);
    float*    p_g2  = sym_p<float>(g_g2);
    uint4*    p_wfc = sym_p<uint4>(g_wfcp);
    uint4*    p_w1  = sym_p<uint4>(g_w1p);
    uint4*    p_w2  = sym_p<uint4>(g_w2p);

    const int dyn = NSTG * STG_BYTES;   // 64 KB
    cudaFuncSetAttribute(tgemm_p_kernel<0>,
                         cudaFuncAttributeMaxDynamicSharedMemorySize, dyn);
    cudaFuncSetAttribute(tgemm_p_kernel<1>,
                         cudaFuncAttributeMaxDynamicSharedMemorySize, dyn);

    // ---- fork: side branch — projections, W2 pack, CSR build
    cudaEventRecord(g_evF, 0);
    cudaStreamWaitEvent(g_side, g_evF, 0);
    proj1_kernel<<<(H1C * 32 + 255) / 256, 256, 0, g_side>>>(W1, a1_src, a1_dst);
    proj2_kernel<<<(DD * 32 + 255) / 256, 256, 0, g_side>>>(W2, a2_src, a2_dst);
    pack_b_kernel<<<((DD / 4) * DD + 255) / 256, 256, 0, g_side>>>(W2, p_w2, DD, DD);
    zero_kernel<<<(NN + 255) / 256, 256, 0, g_side>>>();
    count_kernel<<<(EE + 255) / 256, 256, 0, g_side>>>(adj);
    scan_kernel<<<1, 256, 0, g_side>>>();
    scatter_kernel<<<(EE + 255) / 256, 256, 0, g_side>>>(adj);

    // ---- main branch
    pack_a_kernel<<<(NN * H1C / 2 + 255) / 256, 256>>>(x, p_xp, NN * H1C / 2);
    pack_b_kernel<<<((H1C / 4) * H1C + 255) / 256, 256>>>(W_fc, p_wfc, H1C, H1C);
    pack_b_kernel<<<((H1C / 4) * DD + 255) / 256, 256>>>(W1, p_w1, H1C, DD);

    // fc + relu -> packed h0
    tgemm_p_kernel<1><<<dim3(H1C / 128, NN / 128), 256, dyn>>>(
        p_xp, p_wfc, b_fc, p_h0p, NN, H1C, H1C);
    cudaEventRecord(g_evG1, 0);

    // side: al1 + alpha1 concurrent with GEMM2a/b
    cudaStreamWaitEvent(g_side, g_evG1, 0);
    al1p_kernel<<<(NN * 32 + 255) / 256, 256, 0, g_side>>>();
    alpha1_kernel<<<(NN * 32 + 255) / 256, 256, 0, g_side>>>();
    cudaEventRecord(g_evJ1, g_side);

    // main: GEMM2 column halves (g1 cols [0,256) then [256,512))
    tgemm_p_kernel<0><<<dim3(2, NN / 128), 256, dyn>>>(
        p_h0p, p_w1, nullptr, p_g1, NN, DD, H1C);
    cudaEventRecord(g_evG2a, 0);
    tgemm_p_kernel<0><<<dim3(2, NN / 128), 256, dyn>>>(
        p_h0p, p_w1 + H1C, nullptr, p_g1 + H1C, NN, DD, H1C);

    // side: agg1 half0 concurrent with main's GEMM2b
    cudaStreamWaitEvent(g_side, g_evG2a, 0);   // needs g1 cols 0-255 + alpha1
    agg1h_kernel<<<NN, 64, 0, g_side>>>(b1, 0);
    cudaEventRecord(g_evH0, g_side);

    // main: agg1 half1 (after GEMM2b; alpha1 via evJ1)
    cudaStreamWaitEvent(0, g_evJ1, 0);
    agg1h_kernel<<<NN, 64>>>(b1, 1);
    cudaStreamWaitEvent(0, g_evH0, 0);          // h1p fully written
    cudaEventRecord(g_evA1, 0);

    // side: al2 + alpha2 concurrent with GEMM3a/b
    cudaStreamWaitEvent(g_side, g_evA1, 0);
    al2p_kernel<<<(NN * 32 + 255) / 256, 256, 0, g_side>>>();
    alpha2_kernel<<<(NN * 32 + 255) / 256, 256, 0, g_side>>>();
    cudaEventRecord(g_evJ2, g_side);

    // main: GEMM3 column halves (g2 cols [0,256) then [256,512))
    tgemm_p_kernel<0><<<dim3(2, NN / 128), 256, dyn>>>(
        p_h1p, p_w2, nullptr, p_g2, NN, DD, DD);
    cudaEventRecord(g_evG3a, 0);
    tgemm_p_kernel<0><<<dim3(2, NN / 128), 256, dyn>>>(
        p_h1p, p_w2 + H1C, nullptr, p_g2 + H1C, NN, DD, DD);

    // side: agg2 half0 concurrent with main's GEMM3b (ordered after alpha2 on side)
    cudaStreamWaitEvent(g_side, g_evG3a, 0);
    agg2h_kernel<<<NN, 64, 0, g_side>>>(b2, out, 0);
    cudaEventRecord(g_evH2, g_side);            // terminate side branch

    // main: agg2 half1, then join side branch so capture has no dangling work
    cudaStreamWaitEvent(0, g_evJ2, 0);
    agg2h_kernel<<<NN, 64>>>(b2, out, 1);
    cudaStreamWaitEvent(0, g_evH2, 0);
    join_kernel<<<1, 32>>>();
}

// round 15
// speedup vs baseline: 1.2885x; 1.0074x over previous
#include <cuda_runtime.h>
#include <cuda_bf16.h>
#include <cstdint>

#define NN 16384
#define EE 262144
#define H1C 256
#define DD 512
#define NEG_SLOPE 0.2f

// ---------------- device scratch ----------------
__device__ uint32_t g_xp [NN * H1C];
__device__ uint32_t g_h0p[NN * H1C];
__device__ uint32_t g_h1p[(size_t)NN * DD];
__device__ float    g_g1[(size_t)NN * DD];
__device__ float    g_g2[(size_t)NN * DD];
__device__ uint4 g_wfcp[(H1C / 4) * H1C];
__device__ uint4 g_w1p [(H1C / 4) * DD];
__device__ uint4 g_w2p [(DD / 4) * DD];
__device__ float4 g_P1[H1C];
__device__ float2 g_P2[DD];

__device__ float g_al1[NN * 4];
__device__ float g_al2[NN * 2];
__device__ __align__(16) int g_deg[NN];
__device__ int   g_cursor[NN];
__device__ __align__(16) int g_off[NN + 1];
__device__ int   g_esrc[EE];
__device__ float g_alpha1[(size_t)EE * 2];
__device__ float g_salpha1[NN * 2];
__device__ float g_alpha2[EE];
__device__ float g_salpha2[NN];

// ---------------- streams / events ----------------
static cudaStream_t g_s1 = nullptr, g_s2 = nullptr;
static cudaEvent_t g_evF, g_evG1, g_evJ1, g_evG2a, g_evH0, g_evH1, g_evJ2, g_evA2H0;
namespace {
struct StreamInit {
    StreamInit() {
        cudaStreamCreateWithFlags(&g_s1, cudaStreamNonBlocking);
        cudaStreamCreateWithFlags(&g_s2, cudaStreamNonBlocking);
        cudaEventCreateWithFlags(&g_evF,    cudaEventDisableTiming);
        cudaEventCreateWithFlags(&g_evG1,   cudaEventDisableTiming);
        cudaEventCreateWithFlags(&g_evJ1,   cudaEventDisableTiming);
        cudaEventCreateWithFlags(&g_evG2a,  cudaEventDisableTiming);
        cudaEventCreateWithFlags(&g_evH0,   cudaEventDisableTiming);
        cudaEventCreateWithFlags(&g_evH1,   cudaEventDisableTiming);
        cudaEventCreateWithFlags(&g_evJ2,   cudaEventDisableTiming);
        cudaEventCreateWithFlags(&g_evA2H0, cudaEventDisableTiming);
    }
};
static StreamInit g_si;
}

// ---------------- split helpers ----------------
__device__ __forceinline__ void split_pack(float x0, float x1,
                                           uint32_t& hi, uint32_t& lo) {
    __nv_bfloat16 h0 = __float2bfloat16_rn(x0);
    __nv_bfloat16 h1 = __float2bfloat16_rn(x1);
    hi = (uint32_t)__bfloat16_as_ushort(h0) |
         ((uint32_t)__bfloat16_as_ushort(h1) << 16);
    float l0 = x0 - __bfloat162float(h0);
    float l1 = x1 - __bfloat162float(h1);
    __nv_bfloat162 lp = __floats2bfloat162_rn(l0, l1);
    lo = *reinterpret_cast<const uint32_t*>(&lp);
}
__device__ __forceinline__ float bf_lo(uint32_t w) {
    return __bfloat162float(__ushort_as_bfloat16((unsigned short)(w & 0xffffu)));
}
__device__ __forceinline__ float bf_hi(uint32_t w) {
    return __bfloat162float(__ushort_as_bfloat16((unsigned short)(w >> 16)));
}

// ---------------- pack kernels ----------------
__global__ void pack_a_kernel(const float* __restrict__ X,
                              uint32_t* __restrict__ P, int npairs) {
    int i = blockIdx.x * blockDim.x + threadIdx.x;
    if (i < npairs) {
        float2 v = *(const float2*)(X + 2 * (size_t)i);
        split_pack(v.x, v.y, P[2 * (size_t)i], P[2 * (size_t)i + 1]);
    }
}
__global__ void pack_b_kernel(const float* __restrict__ W,
                              uint4* __restrict__ P, int K, int N) {
    int idx = blockIdx.x * blockDim.x + threadIdx.x;
    int total = (K / 4) * N;
    if (idx >= total) return;
    int c = idx / N;
    int n = idx - c * N;
    const float* wp = W + (size_t)(4 * c) * N + n;
    uint4 o;
    split_pack(wp[0], wp[N], o.x, o.y);
    split_pack(wp[2 * N], wp[3 * N], o.z, o.w);
    P[idx] = o;
}

// ---------------- projection kernels ----------------
__global__ void proj1_kernel(const float* __restrict__ W1,
                             const float* __restrict__ a1s,
                             const float* __restrict__ a1d) {
    int k = (blockIdx.x * blockDim.x + threadIdx.x) >> 5;
    if (k >= H1C) return;
    int lane = threadIdx.x & 31;
    const float* wr = W1 + (size_t)k * DD;
    float s0 = 0.f, s1 = 0.f, d0 = 0.f, d1 = 0.f;
    for (int c = lane; c < H1C; c += 32) {
        float w0 = wr[c];
        float w1 = wr[H1C + c];
        s0 = fmaf(w0, a1s[c], s0);
        s1 = fmaf(w1, a1s[H1C + c], s1);
        d0 = fmaf(w0, a1d[c], d0);
        d1 = fmaf(w1, a1d[H1C + c], d1);
    }
    #pragma unroll
    for (int o = 16; o; o >>= 1) {
        s0 += __shfl_down_sync(0xffffffffu, s0, o);
        s1 += __shfl_down_sync(0xffffffffu, s1, o);
        d0 += __shfl_down_sync(0xffffffffu, d0, o);
        d1 += __shfl_down_sync(0xffffffffu, d1, o);
    }
    if (lane == 0) g_P1[k] = make_float4(s0, s1, d0, d1);
}
__global__ void proj2_kernel(const float* __restrict__ W2,
                             const float* __restrict__ a2s,
                             const float* __restrict__ a2d) {
    int k = (blockIdx.x * blockDim.x + threadIdx.x) >> 5;
    if (k >= DD) return;
    int lane = threadIdx.x & 31;
    const float* wr = W2 + (size_t)k * DD;
    float s = 0.f, d = 0.f;
    for (int c = lane; c < DD; c += 32) {
        float w = wr[c];
        s = fmaf(w, a2s[c], s);
        d = fmaf(w, a2d[c], d);
    }
    #pragma unroll
    for (int o = 16; o; o >>= 1) {
        s += __shfl_down_sync(0xffffffffu, s, o);
        d += __shfl_down_sync(0xffffffffu, d, o);
    }
    if (lane == 0) g_P2[k] = make_float2(s, d);
}

// ---------------- CSR ----------------
__global__ void zero_kernel() {
    int i = blockIdx.x * blockDim.x + threadIdx.x;
    if (i < NN) { g_deg[i] = 0; g_cursor[i] = 0; }
}
__global__ void count_kernel(const int* __restrict__ adj) {
    int i = blockIdx.x * blockDim.x + threadIdx.x;
    if (i < EE) atomicAdd(&g_deg[adj[EE + i]], 1);
}
__global__ void scan_kernel() {
    int t = threadIdx.x;
    int4 v[16];
    const int4* dp = (const int4*)g_deg + t * 16;
    #pragma unroll
    for (int k = 0; k < 16; k++) v[k] = dp[k];
    int sum = 0;
    #pragma unroll
    for (int k = 0; k < 16; k++) sum += v[k].x + v[k].y + v[k].z + v[k].w;
    __shared__ int part[256];
    part[t] = sum;
    __syncthreads();
    for (int s = 1; s < 256; s <<= 1) {
        int q = (t >= s) ? part[t - s] : 0;
        __syncthreads();
        part[t] += q;
        __syncthreads();
    }
    int run = (t > 0) ? part[t - 1] : 0;
    int4* op = (int4*)g_off + t * 16;
    #pragma unroll
    for (int k = 0; k < 16; k++) {
        int4 o;
        o.x = run; run += v[k].x;
        o.y = run; run += v[k].y;
        o.z = run; run += v[k].z;
        o.w = run; run += v[k].w;
        op[k] = o;
    }
    if (t == 255) g_off[NN] = run;
}
__global__ void scatter_kernel(const int* __restrict__ adj) {
    int i = blockIdx.x * blockDim.x + threadIdx.x;
    if (i < EE) {
        int src = adj[i];
        int dst = adj[EE + i];
        int p = g_off[dst] + atomicAdd(&g_cursor[dst], 1);
        g_esrc[p] = src;
    }
}

// ================= Tensor-core GEMM (bf16x3, cp.async pipeline) =================
__device__ __forceinline__ int smw(int outer, int kw) {
    int line = outer >> 1;
    int M = ((line & 3) << 1) | ((line >> 2) & 1);
    int lc = ((outer & 1) << 2) + (kw >> 1);
    return line * 32 + (((lc ^ M) << 2) | ((kw & 1) << 1));
}
__device__ __forceinline__ void mma16816(float* d, const uint32_t* a,
                                         const uint32_t* b) {
    asm volatile(
        "mma.sync.aligned.m16n8k16.row.col.f32.bf16.bf16.f32 "
        "{%0,%1,%2,%3}, {%4,%5,%6,%7}, {%8,%9}, {%0,%1,%2,%3};\n"
        : "+f"(d[0]), "+f"(d[1]), "+f"(d[2]), "+f"(d[3])
        : "r"(a[0]), "r"(a[1]), "r"(a[2]), "r"(a[3]),
          "r"(b[0]), "r"(b[1]));
}
__device__ __forceinline__ uint32_t smem_u32(const void* p) {
    uint32_t a;
    asm("{ .reg .u64 t; cvta.to.shared.u64 t, %1; cvt.u32.u64 %0, t; }"
        : "=r"(a) : "l"(p));
    return a;
}
__device__ __forceinline__ void cp16(uint32_t dst, const void* src) {
    asm volatile("cp.async.cg.shared.global [%0], [%1], 16;"
                 :: "r"(dst), "l"(src));
}
#define CP_COMMIT() asm volatile("cp.async.commit_group;" ::: "memory")
#define STG_BYTES 16384
#define NSTG 4

__device__ __forceinline__ void fill_stage(
    const uint32_t* __restrict__ Ap, const uint4* __restrict__ Bp,
    int brow, int bcol, int lda, int N, int k0, int tid, uint32_t sbase)
{
    int c4 = tid & 3;
    #pragma unroll
    for (int f = 0; f < 2; f++) {
        int row = (tid >> 2) + 64 * f;
        cp16(sbase + 4 * smw(row, 2 * c4),
             Ap + (size_t)(brow + row) * lda + k0 + 4 * c4);
    }
    int tc = tid >> 6;
    int m  = tid & 63;
    const uint4* bp = Bp + (size_t)((k0 >> 2) + tc) * N + bcol + 2 * m;
    uint32_t bB = sbase + 8192;
    cp16(bB + 4 * smw(2 * m,     2 * tc), bp);
    cp16(bB + 4 * smw(2 * m + 1, 2 * tc), bp + 1);
}

// OUT_MODE: 0 = fp32 write, 1 = packed split-bf16 w/ bias+relu, 2 = fp32 accumulate (C += A@B)
// N = row stride of B/C (columns covered = gridDim.x*128; callers pre-offset Bp/Cout).
// lda = row stride of A (words); K = reduction extent.
template <int OUT_MODE>
__global__ __launch_bounds__(256, 2) void tgemm_p_kernel(
    const uint32_t* __restrict__ Ap, const uint4* __restrict__ Bp,
    const float* __restrict__ bias, void* __restrict__ Cout,
    int M, int N, int K, int lda)
{
    extern __shared__ uint32_t dynsm[];
    const uint32_t sb = smem_u32(dynsm);

    const int tid  = threadIdx.x;
    const int lane = tid & 31;
    const int wid  = tid >> 5;
    const int wm   = wid & 1;
    const int wn   = wid >> 1;
    const int brow = blockIdx.y * 128;
    const int bcol = blockIdx.x * 128;

    float acc[4][4][4];
    #pragma unroll
    for (int i = 0; i < 4; i++)
        #pragma unroll
        for (int j = 0; j < 4; j++)
            #pragma unroll
            for (int q = 0; q < 4; q++) acc[i][j][q] = 0.f;

    const int iters = K >> 4;

    #pragma unroll
    for (int s = 0; s < NSTG - 1; s++) {
        if (s < iters) {
            fill_stage(Ap, Bp, brow, bcol, lda, N, s << 4, tid, sb + s * STG_BYTES);
            CP_COMMIT();
        }
    }

    const int c  = lane & 3;
    const int r4 = lane >> 2;
    const int offA0 = smw(r4, c);
    const int offA1 = smw(8 + r4, c);
    const int offA2 = smw(r4, c + 4);
    const int offA3 = smw(8 + r4, c + 4);

    for (int it = 0; it < iters; ++it) {
        int rem = iters - 1 - it;
        if (rem >= 2)      asm volatile("cp.async.wait_group 2;" ::: "memory");
        else if (rem == 1) asm volatile("cp.async.wait_group 1;" ::: "memory");
        else               asm volatile("cp.async.wait_group 0;" ::: "memory");
        __syncthreads();

        uint32_t* buf  = dynsm + (it & (NSTG - 1)) * 4096;
        uint32_t* Abuf = buf;
        uint32_t* Bbuf = buf + 2048;

        uint2 bfr[4][2];
        #pragma unroll
        for (int ni = 0; ni < 4; ni++) {
            int base = wn * 512;
            bfr[ni][0] = *(const uint2*)&Bbuf[base + smw(ni * 8 + r4, c)];
            bfr[ni][1] = *(const uint2*)&Bbuf[base + smw(ni * 8 + r4, c + 4)];
        }
        #pragma unroll
        for (int mi = 0; mi < 4; mi++) {
            int base = (wm * 64 + mi * 16) * 16;
            uint2 a0 = *(const uint2*)&Abuf[base + offA0];
            uint2 a1 = *(const uint2*)&Abuf[base + offA1];
            uint2 a2 = *(const uint2*)&Abuf[base + offA2];
            uint2 a3 = *(const uint2*)&Abuf[base + offA3];
            uint32_t ah[4] = {a0.x, a1.x, a2.x, a3.x};
            uint32_t al[4] = {a0.y, a1.y, a2.y, a3.y};
            #pragma unroll
            for (int ni = 0; ni < 4; ni++) {
                uint32_t bh[2] = {bfr[ni][0].x, bfr[ni][1].x};
                uint32_t bl[2] = {bfr[ni][0].y, bfr[ni][1].y};
                mma16816(acc[mi][ni], ah, bh);
                mma16816(acc[mi][ni], ah, bl);
                mma16816(acc[mi][ni], al, bh);
            }
        }

        if (it + NSTG - 1 < iters) {
            fill_stage(Ap, Bp, brow, bcol, lda, N, (it + NSTG - 1) << 4, tid,
                       sb + ((it + NSTG - 1) & (NSTG - 1)) * STG_BYTES);
            CP_COMMIT();
        }
    }

    #pragma unroll
    for (int mi = 0; mi < 4; mi++) {
        int row = brow + wm * 64 + mi * 16 + r4;
        #pragma unroll
        for (int ni = 0; ni < 4; ni++) {
            int col = bcol + wn * 32 + ni * 8 + 2 * c;
            float2 v0 = make_float2(acc[mi][ni][0], acc[mi][ni][1]);
            float2 v1 = make_float2(acc[mi][ni][2], acc[mi][ni][3]);
            if (OUT_MODE == 1) {
                float2 bb = *(const float2*)(bias + col);
                v0.x = fmaxf(v0.x + bb.x, 0.f); v0.y = fmaxf(v0.y + bb.y, 0.f);
                v1.x = fmaxf(v1.x + bb.x, 0.f); v1.y = fmaxf(v1.y + bb.y, 0.f);
                uint2 w0, w1;
                split_pack(v0.x, v0.y, w0.x, w0.y);
                split_pack(v1.x, v1.y, w1.x, w1.y);
                uint32_t* P = (uint32_t*)Cout;
                *(uint2*)(P + (size_t)row * N + col)       = w0;
                *(uint2*)(P + (size_t)(row + 8) * N + col) = w1;
            } else {
                float* C = (float*)Cout;
                float* c0 = C + (size_t)row * N + col;
                float* c1 = C + (size_t)(row + 8) * N + col;
                if (OUT_MODE == 2) {
                    float2 o0 = *(float2*)c0;
                    float2 o1 = *(float2*)c1;
                    v0.x += o0.x; v0.y += o0.y;
                    v1.x += o1.x; v1.y += o1.y;
                }
                *(float2*)c0 = v0;
                *(float2*)c1 = v1;
            }
        }
    }
}

// ---------------- attention scalars from packed h via projections ----------------
__global__ void al1p_kernel() {
    int n = (blockIdx.x * blockDim.x + threadIdx.x) >> 5;
    if (n >= NN) return;
    int lane = threadIdx.x & 31;
    const uint2* row = (const uint2*)(g_h0p + (size_t)n * H1C);
    float s0 = 0.f, s1 = 0.f, d0 = 0.f, d1 = 0.f;
    for (int i = lane; i < 128; i += 32) {
        uint2 w = row[i];
        float x0 = bf_lo(w.x) + bf_lo(w.y);
        float x1 = bf_hi(w.x) + bf_hi(w.y);
        float4 p0 = g_P1[2 * i];
        float4 p1 = g_P1[2 * i + 1];
        s0 += x0 * p0.x + x1 * p1.x;
        s1 += x0 * p0.y + x1 * p1.y;
        d0 += x0 * p0.z + x1 * p1.z;
        d1 += x0 * p0.w + x1 * p1.w;
    }
    #pragma unroll
    for (int o = 16; o; o >>= 1) {
        s0 += __shfl_down_sync(0xffffffffu, s0, o);
        s1 += __shfl_down_sync(0xffffffffu, s1, o);
        d0 += __shfl_down_sync(0xffffffffu, d0, o);
        d1 += __shfl_down_sync(0xffffffffu, d1, o);
    }
    if (lane == 0) ((float4*)g_al1)[n] = make_float4(s0, s1, d0, d1);
}

__global__ void al2p_kernel() {
    int n = (blockIdx.x * blockDim.x + threadIdx.x) >> 5;
    if (n >= NN) return;
    int lane = threadIdx.x & 31;
    const uint2* row = (const uint2*)(g_h1p + (size_t)n * DD);
    float s = 0.f, d = 0.f;
    for (int i = lane; i < 256; i += 32) {
        uint2 w = row[i];
        float x0 = bf_lo(w.x) + bf_lo(w.y);
        float x1 = bf_hi(w.x) + bf_hi(w.y);
        float2 p0 = g_P2[2 * i];
        float2 p1 = g_P2[2 * i + 1];
        s += x0 * p0.x + x1 * p1.x;
        d += x0 * p0.y + x1 * p1.y;
    }
    #pragma unroll
    for (int o = 16; o; o >>= 1) {
        s += __shfl_down_sync(0xffffffffu, s, o);
        d += __shfl_down_sync(0xffffffffu, d, o);
    }
    if (lane == 0) ((float2*)g_al2)[n] = make_float2(s, d);
}

__device__ __forceinline__ float lrelu(float x) {
    return x > 0.f ? x : NEG_SLOPE * x;
}

// ---------------- edge softmax ----------------
__global__ void alpha1_kernel() {
    int n = (blockIdx.x * blockDim.x + threadIdx.x) >> 5;
    if (n >= NN) return;
    int lane = threadIdx.x & 31;
    int o = g_off[n];
    int cnt = g_off[n + 1] - o;
    float dd0 = g_al1[n * 4 + 2];
    float dd1 = g_al1[n * 4 + 3];

    float m0 = -1e30f, m1 = -1e30f;
    for (int i = lane; i <= cnt; i += 32) {
        int s = (i < cnt) ? g_esrc[o + i] : n;
        m0 = fmaxf(m0, lrelu(g_al1[s * 4 + 0] + dd0));
        m1 = fmaxf(m1, lrelu(g_al1[s * 4 + 1] + dd1));
    }
    #pragma unroll
    for (int x = 16; x; x >>= 1) {
        m0 = fmaxf(m0, __shfl_xor_sync(0xffffffffu, m0, x));
        m1 = fmaxf(m1, __shfl_xor_sync(0xffffffffu, m1, x));
    }
    float sum0 = 0.f, sum1 = 0.f;
    for (int i = lane; i <= cnt; i += 32) {
        int s = (i < cnt) ? g_esrc[o + i] : n;
        sum0 += expf(lrelu(g_al1[s * 4 + 0] + dd0) - m0);
        sum1 += expf(lrelu(g_al1[s * 4 + 1] + dd1) - m1);
    }
    #pragma unroll
    for (int x = 16; x; x >>= 1) {
        sum0 += __shfl_xor_sync(0xffffffffu, sum0, x);
        sum1 += __shfl_xor_sync(0xffffffffu, sum1, x);
    }
    float inv0 = 1.f / (sum0 + 1e-16f);
    float inv1 = 1.f / (sum1 + 1e-16f);
    for (int i = lane; i <= cnt; i += 32) {
        int s = (i < cnt) ? g_esrc[o + i] : n;
        float a0 = expf(lrelu(g_al1[s * 4 + 0] + dd0) - m0) * inv0;
        float a1 = expf(lrelu(g_al1[s * 4 + 1] + dd1) - m1) * inv1;
        if (i < cnt) {
            g_alpha1[(size_t)(o + i) * 2 + 0] = a0;
            g_alpha1[(size_t)(o + i) * 2 + 1] = a1;
        } else {
            g_salpha1[n * 2 + 0] = a0;
            g_salpha1[n * 2 + 1] = a1;
        }
    }
}

__global__ void alpha2_kernel() {
    int n = (blockIdx.x * blockDim.x + threadIdx.x) >> 5;
    if (n >= NN) return;
    int lane = threadIdx.x & 31;
    int o = g_off[n];
    int cnt = g_off[n + 1] - o;
    float dd = g_al2[n * 2 + 1];

    float m = -1e30f;
    for (int i = lane; i <= cnt; i += 32) {
        int s = (i < cnt) ? g_esrc[o + i] : n;
        m = fmaxf(m, lrelu(g_al2[s * 2] + dd));
    }
    #pragma unroll
    for (int x = 16; x; x >>= 1)
        m = fmaxf(m, __shfl_xor_sync(0xffffffffu, m, x));
    float sum = 0.f;
    for (int i = lane; i <= cnt; i += 32) {
        int s = (i < cnt) ? g_esrc[o + i] : n;
        sum += expf(lrelu(g_al2[s * 2] + dd) - m);
    }
    #pragma unroll
    for (int x = 16; x; x >>= 1)
        sum += __shfl_xor_sync(0xffffffffu, sum, x);
    float inv = 1.f / (sum + 1e-16f);
    for (int i = lane; i <= cnt; i += 32) {
        int s = (i < cnt) ? g_esrc[o + i] : n;
        float a = expf(lrelu(g_al2[s * 2] + dd) - m) * inv;
        if (i < cnt) g_alpha2[o + i] = a;
        else g_salpha2[n] = a;
    }
}

// ---------------- aggregation halves ----------------
__global__ __launch_bounds__(64) void agg1h_kernel(const float* __restrict__ b1,
                                                   int head) {
    int n = blockIdx.x;
    int tid = threadIdx.x;
    int o = g_off[n];
    int cnt = g_off[n + 1] - o;

    __shared__ int   ssrc[64];
    __shared__ float sal[64];

    const float* gbase = g_g1 + (size_t)head * H1C;
    float4 acc = make_float4(0.f, 0.f, 0.f, 0.f);
    for (int base = 0; base < cnt; base += 64) {
        int m = min(64, cnt - base);
        if (tid < m) {
            int e = o + base + tid;
            ssrc[tid] = g_esrc[e];
            sal[tid] = g_alpha1[(size_t)e * 2 + head];
        }
        __syncthreads();
        for (int j = 0; j < m; j++) {
            float a = sal[j];
            float4 v = ((const float4*)(gbase + (size_t)ssrc[j] * DD))[tid];
            acc.x = fmaf(a, v.x, acc.x);
            acc.y = fmaf(a, v.y, acc.y);
            acc.z = fmaf(a, v.z, acc.z);
            acc.w = fmaf(a, v.w, acc.w);
        }
        __syncthreads();
    }
    {
        float a = g_salpha1[n * 2 + head];
        float4 v = ((const float4*)(gbase + (size_t)n * DD))[tid];
        acc.x = fmaf(a, v.x, acc.x);
        acc.y = fmaf(a, v.y, acc.y);
        acc.z = fmaf(a, v.z, acc.z);
        acc.w = fmaf(a, v.w, acc.w);
    }
    float4 bb = ((const float4*)(b1 + head * H1C))[tid];
    acc.x = fmaxf(acc.x + bb.x, 0.f);
    acc.y = fmaxf(acc.y + bb.y, 0.f);
    acc.z = fmaxf(acc.z + bb.z, 0.f);
    acc.w = fmaxf(acc.w + bb.w, 0.f);
    uint4 w;
    split_pack(acc.x, acc.y, w.x, w.y);
    split_pack(acc.z, acc.w, w.z, w.w);
    *(uint4*)(g_h1p + (size_t)n * DD + head * H1C + 4 * tid) = w;
}

__global__ __launch_bounds__(64) void agg2h_kernel(const float* __restrict__ b2,
                                                   float* __restrict__ out,
                                                   int half) {
    int n = blockIdx.x;
    int tid = threadIdx.x;
    int o = g_off[n];
    int cnt = g_off[n + 1] - o;

    __shared__ int   ssrc[64];
    __shared__ float sal[64];

    const float* gbase = g_g2 + (size_t)half * H1C;
    float4 acc = make_float4(0.f, 0.f, 0.f, 0.f);
    for (int base = 0; base < cnt; base += 64) {
        int m = min(64, cnt - base);
        if (tid < m) {
            ssrc[tid] = g_esrc[o + base + tid];
            sal[tid] = g_alpha2[o + base + tid];
        }
        __syncthreads();
        for (int j = 0; j < m; j++) {
            float a = sal[j];
            float4 v = ((const float4*)(gbase + (size_t)ssrc[j] * DD))[tid];
            acc.x = fmaf(a, v.x, acc.x);
            acc.y = fmaf(a, v.y, acc.y);
            acc.z = fmaf(a, v.z, acc.z);
            acc.w = fmaf(a, v.w, acc.w);
        }
        __syncthreads();
    }
    {
        float a = g_salpha2[n];
        float4 v = ((const float4*)(gbase + (size_t)n * DD))[tid];
        acc.x = fmaf(a, v.x, acc.x);
        acc.y = fmaf(a, v.y, acc.y);
        acc.z = fmaf(a, v.z, acc.z);
        acc.w = fmaf(a, v.w, acc.w);
    }
    float4 bb = ((const float4*)(b2 + half * H1C))[tid];
    acc.x = fmaxf(acc.x + bb.x, 0.f);
    acc.y = fmaxf(acc.y + bb.y, 0.f);
    acc.z = fmaxf(acc.z + bb.z, 0.f);
    acc.w = fmaxf(acc.w + bb.w, 0.f);
    *(float4*)(out + (size_t)n * DD + half * H1C + 4 * tid) = acc;
}

__global__ void join_kernel() {}

// ---------------- launcher ----------------
template <typename T>
static T* sym_p(const void* sym) {
    void* p = nullptr;
    cudaGetSymbolAddress(&p, sym);
    return (T*)p;
}

extern "C" void kernel_launch(void* const* d_in, const int* in_sizes, int n_in,
                              void* d_out, int out_size) {
    const float* x      = (const float*)d_in[0];
    const int*   adj    = (const int*)d_in[1];
    const float* W_fc   = (const float*)d_in[2];
    const float* b_fc   = (const float*)d_in[3];
    const float* W1     = (const float*)d_in[4];
    const float* a1_src = (const float*)d_in[5];
    const float* a1_dst = (const float*)d_in[6];
    const float* b1     = (const float*)d_in[7];
    const float* W2     = (const float*)d_in[8];
    const float* a2_src = (const float*)d_in[9];
    const float* a2_dst = (const float*)d_in[10];
    const float* b2     = (const float*)d_in[11];
    float* out = (float*)d_out;

    uint32_t* p_xp  = sym_p<uint32_t>(g_xp);
    uint32_t* p_h0p = sym_p<uint32_t>(g_h0p);
    uint32_t* p_h1p = sym_p<uint32_t>(g_h1p);
    float*    p_g1  = sym_p<float>(g_g1);
    float*    p_g2  = sym_p<float>(g_g2);
    uint4*    p_wfc = sym_p<uint4>(g_wfcp);
    uint4*    p_w1  = sym_p<uint4>(g_w1p);
    uint4*    p_w2  = sym_p<uint4>(g_w2p);

    const int dyn = NSTG * STG_BYTES;   // 64 KB
    cudaFuncSetAttribute(tgemm_p_kernel<0>,
                         cudaFuncAttributeMaxDynamicSharedMemorySize, dyn);
    cudaFuncSetAttribute(tgemm_p_kernel<1>,
                         cudaFuncAttributeMaxDynamicSharedMemorySize, dyn);
    cudaFuncSetAttribute(tgemm_p_kernel<2>,
                         cudaFuncAttributeMaxDynamicSharedMemorySize, dyn);

    // ---- fork s1: projections, W2 pack, CSR build
    cudaEventRecord(g_evF, 0);
    cudaStreamWaitEvent(g_s1, g_evF, 0);
    proj1_kernel<<<(H1C * 32 + 255) / 256, 256, 0, g_s1>>>(W1, a1_src, a1_dst);
    proj2_kernel<<<(DD * 32 + 255) / 256, 256, 0, g_s1>>>(W2, a2_src, a2_dst);
    pack_b_kernel<<<((DD / 4) * DD + 255) / 256, 256, 0, g_s1>>>(W2, p_w2, DD, DD);
    zero_kernel<<<(NN + 255) / 256, 256, 0, g_s1>>>();
    count_kernel<<<(EE + 255) / 256, 256, 0, g_s1>>>(adj);
    scan_kernel<<<1, 256, 0, g_s1>>>();
    scatter_kernel<<<(EE + 255) / 256, 256, 0, g_s1>>>(adj);

    // ---- main: packs + GEMM1
    pack_a_kernel<<<(NN * H1C / 2 + 255) / 256, 256>>>(x, p_xp, NN * H1C / 2);
    pack_b_kernel<<<((H1C / 4) * H1C + 255) / 256, 256>>>(W_fc, p_wfc, H1C, H1C);
    pack_b_kernel<<<((H1C / 4) * DD + 255) / 256, 256>>>(W1, p_w1, H1C, DD);
    tgemm_p_kernel<1><<<dim3(H1C / 128, NN / 128), 256, dyn>>>(
        p_xp, p_wfc, b_fc, p_h0p, NN, H1C, H1C, H1C);
    cudaEventRecord(g_evG1, 0);

    // s1: al1 + alpha1 concurrent with GEMM2a/b
    cudaStreamWaitEvent(g_s1, g_evG1, 0);
    al1p_kernel<<<(NN * 32 + 255) / 256, 256, 0, g_s1>>>();
    alpha1_kernel<<<(NN * 32 + 255) / 256, 256, 0, g_s1>>>();
    cudaEventRecord(g_evJ1, g_s1);

    // main: GEMM2 column halves (g1 N0, then N1)
    tgemm_p_kernel<0><<<dim3(2, NN / 128), 256, dyn>>>(
        p_h0p, p_w1, nullptr, p_g1, NN, DD, H1C, H1C);
    cudaEventRecord(g_evG2a, 0);
    tgemm_p_kernel<0><<<dim3(2, NN / 128), 256, dyn>>>(
        p_h0p, p_w1 + H1C, nullptr, p_g1 + H1C, NN, DD, H1C, H1C);

    // s1: agg1 head0 (h1p K-half0), then G3(N0,K0) — overlaps main's GEMM2b/agg1h1
    cudaStreamWaitEvent(g_s1, g_evG2a, 0);
    agg1h_kernel<<<NN, 64, 0, g_s1>>>(b1, 0);
    cudaEventRecord(g_evH0, g_s1);
    tgemm_p_kernel<0><<<dim3(2, NN / 128), 256, dyn, g_s1>>>(
        p_h1p, p_w2, nullptr, p_g2, NN, DD, H1C, DD);

    // main: agg1 head1 (h1p K-half1) — after GEMM2b (own) + alpha1
    cudaStreamWaitEvent(0, g_evJ1, 0);
    agg1h_kernel<<<NN, 64>>>(b1, 1);
    cudaEventRecord(g_evH1, 0);

    // s2: al2 + alpha2 once full h1p exists — overlaps GEMM3 work
    cudaStreamWaitEvent(g_s2, g_evH0, 0);
    cudaStreamWaitEvent(g_s2, g_evH1, 0);
    al2p_kernel<<<(NN * 32 + 255) / 256, 256, 0, g_s2>>>();
    alpha2_kernel<<<(NN * 32 + 255) / 256, 256, 0, g_s2>>>();
    cudaEventRecord(g_evJ2, g_s2);

    // s1: G3(N0,K1) accumulate — needs h1p K-half1
    cudaStreamWaitEvent(g_s1, g_evH1, 0);
    tgemm_p_kernel<2><<<dim3(2, NN / 128), 256, dyn, g_s1>>>(
        p_h1p + H1C, p_w2 + (size_t)(H1C / 4) * DD, nullptr, p_g2,
        NN, DD, H1C, DD);

    // main: G3(N1,K0) then G3(N1,K1) accumulate
    cudaStreamWaitEvent(0, g_evH0, 0);
    tgemm_p_kernel<0><<<dim3(2, NN / 128), 256, dyn>>>(
        p_h1p, p_w2 + H1C, nullptr, p_g2 + H1C, NN, DD, H1C, DD);
    tgemm_p_kernel<2><<<dim3(2, NN / 128), 256, dyn>>>(
        p_h1p + H1C, p_w2 + (size_t)(H1C / 4) * DD + H1C, nullptr, p_g2 + H1C,
        NN, DD, H1C, DD);

    // s1: agg2 half0 (g2 N0 complete on s1) — overlaps main's G3(N1,K1)
    cudaStreamWaitEvent(g_s1, g_evJ2, 0);
    agg2h_kernel<<<NN, 64, 0, g_s1>>>(b2, out, 0);
    cudaEventRecord(g_evA2H0, g_s1);

    // main: agg2 half1, then join all branches
    cudaStreamWaitEvent(0, g_evJ2, 0);
    agg2h_kernel<<<NN, 64>>>(b2, out, 1);
    cudaStreamWaitEvent(0, g_evA2H0, 0);
    join_kernel<<<1, 32>>>();
}

// round 16
// speedup vs baseline: 1.3066x; 1.0141x over previous
#include <cuda_runtime.h>
#include <cuda_bf16.h>
#include <cstdint>

#define NN 16384
#define EE 262144
#define H1C 256
#define DD 512
#define NEG_SLOPE 0.2f

// ---------------- device scratch ----------------
__device__ uint32_t g_xp [NN * H1C];
__device__ uint32_t g_h0p[NN * H1C];
__device__ uint32_t g_h1p[(size_t)NN * DD];
__device__ float    g_g1[(size_t)NN * DD];
__device__ float    g_g2[(size_t)NN * DD];
__device__ uint4 g_wfcp[(H1C / 4) * H1C];
__device__ uint4 g_w1p [(H1C / 4) * DD];
__device__ uint4 g_w2p [(DD / 4) * DD];
__device__ float4 g_P1[H1C];
__device__ float2 g_P2[DD];

__device__ float g_al1[NN * 4];
__device__ float2 g_al2a[NN];   // contribution from h1 half0
__device__ float2 g_al2b[NN];   // contribution from h1 half1
__device__ __align__(16) int g_deg[NN];
__device__ int   g_cursor[NN];
__device__ __align__(16) int g_off[NN + 1];
__device__ int   g_esrc[EE];
__device__ float g_alpha1[(size_t)EE * 2];
__device__ float g_salpha1[NN * 2];
__device__ float g_alpha2[EE];
__device__ float g_salpha2[NN];

// ---------------- streams / events ----------------
static cudaStream_t g_s1 = nullptr, g_s2 = nullptr;
static cudaEvent_t g_evF, g_evG1, g_evJ1, g_evG2a, g_evH0, g_evH1, g_evJ2, g_evA2H0, g_evWP;
namespace {
struct StreamInit {
    StreamInit() {
        cudaStreamCreateWithFlags(&g_s1, cudaStreamNonBlocking);
        cudaStreamCreateWithFlags(&g_s2, cudaStreamNonBlocking);
        cudaEventCreateWithFlags(&g_evF,    cudaEventDisableTiming);
        cudaEventCreateWithFlags(&g_evG1,   cudaEventDisableTiming);
        cudaEventCreateWithFlags(&g_evJ1,   cudaEventDisableTiming);
        cudaEventCreateWithFlags(&g_evG2a,  cudaEventDisableTiming);
        cudaEventCreateWithFlags(&g_evH0,   cudaEventDisableTiming);
        cudaEventCreateWithFlags(&g_evH1,   cudaEventDisableTiming);
        cudaEventCreateWithFlags(&g_evJ2,   cudaEventDisableTiming);
        cudaEventCreateWithFlags(&g_evA2H0, cudaEventDisableTiming);
        cudaEventCreateWithFlags(&g_evWP,   cudaEventDisableTiming);
    }
};
static StreamInit g_si;
}

// ---------------- split helpers ----------------
__device__ __forceinline__ void split_pack(float x0, float x1,
                                           uint32_t& hi, uint32_t& lo) {
    __nv_bfloat16 h0 = __float2bfloat16_rn(x0);
    __nv_bfloat16 h1 = __float2bfloat16_rn(x1);
    hi = (uint32_t)__bfloat16_as_ushort(h0) |
         ((uint32_t)__bfloat16_as_ushort(h1) << 16);
    float l0 = x0 - __bfloat162float(h0);
    float l1 = x1 - __bfloat162float(h1);
    __nv_bfloat162 lp = __floats2bfloat162_rn(l0, l1);
    lo = *reinterpret_cast<const uint32_t*>(&lp);
}
__device__ __forceinline__ float bf_lo(uint32_t w) {
    return __bfloat162float(__ushort_as_bfloat16((unsigned short)(w & 0xffffu)));
}
__device__ __forceinline__ float bf_hi(uint32_t w) {
    return __bfloat162float(__ushort_as_bfloat16((unsigned short)(w >> 16)));
}

// ---------------- pack kernels ----------------
__global__ void pack_a_kernel(const float* __restrict__ X,
                              uint32_t* __restrict__ P, int npairs) {
    int i = blockIdx.x * blockDim.x + threadIdx.x;
    if (i < npairs) {
        float2 v = *(const float2*)(X + 2 * (size_t)i);
        split_pack(v.x, v.y, P[2 * (size_t)i], P[2 * (size_t)i + 1]);
    }
}
__global__ void pack_b_kernel(const float* __restrict__ W,
                              uint4* __restrict__ P, int K, int N) {
    int idx = blockIdx.x * blockDim.x + threadIdx.x;
    int total = (K / 4) * N;
    if (idx >= total) return;
    int c = idx / N;
    int n = idx - c * N;
    const float* wp = W + (size_t)(4 * c) * N + n;
    uint4 o;
    split_pack(wp[0], wp[N], o.x, o.y);
    split_pack(wp[2 * N], wp[3 * N], o.z, o.w);
    P[idx] = o;
}

// ---------------- projection kernels ----------------
__global__ void proj1_kernel(const float* __restrict__ W1,
                             const float* __restrict__ a1s,
                             const float* __restrict__ a1d) {
    int k = (blockIdx.x * blockDim.x + threadIdx.x) >> 5;
    if (k >= H1C) return;
    int lane = threadIdx.x & 31;
    const float* wr = W1 + (size_t)k * DD;
    float s0 = 0.f, s1 = 0.f, d0 = 0.f, d1 = 0.f;
    for (int c = lane; c < H1C; c += 32) {
        float w0 = wr[c];
        float w1 = wr[H1C + c];
        s0 = fmaf(w0, a1s[c], s0);
        s1 = fmaf(w1, a1s[H1C + c], s1);
        d0 = fmaf(w0, a1d[c], d0);
        d1 = fmaf(w1, a1d[H1C + c], d1);
    }
    #pragma unroll
    for (int o = 16; o; o >>= 1) {
        s0 += __shfl_down_sync(0xffffffffu, s0, o);
        s1 += __shfl_down_sync(0xffffffffu, s1, o);
        d0 += __shfl_down_sync(0xffffffffu, d0, o);
        d1 += __shfl_down_sync(0xffffffffu, d1, o);
    }
    if (lane == 0) g_P1[k] = make_float4(s0, s1, d0, d1);
}
__global__ void proj2_kernel(const float* __restrict__ W2,
                             const float* __restrict__ a2s,
                             const float* __restrict__ a2d) {
    int k = (blockIdx.x * blockDim.x + threadIdx.x) >> 5;
    if (k >= DD) return;
    int lane = threadIdx.x & 31;
    const float* wr = W2 + (size_t)k * DD;
    float s = 0.f, d = 0.f;
    for (int c = lane; c < DD; c += 32) {
        float w = wr[c];
        s = fmaf(w, a2s[c], s);
        d = fmaf(w, a2d[c], d);
    }
    #pragma unroll
    for (int o = 16; o; o >>= 1) {
        s += __shfl_down_sync(0xffffffffu, s, o);
        d += __shfl_down_sync(0xffffffffu, d, o);
    }
    if (lane == 0) g_P2[k] = make_float2(s, d);
}

// ---------------- CSR ----------------
__global__ void zero_kernel() {
    int i = blockIdx.x * blockDim.x + threadIdx.x;
    if (i < NN) { g_deg[i] = 0; g_cursor[i] = 0; }
}
__global__ void count_kernel(const int* __restrict__ adj) {
    int i = blockIdx.x * blockDim.x + threadIdx.x;
    if (i < EE) atomicAdd(&g_deg[adj[EE + i]], 1);
}
__global__ void scan_kernel() {
    int t = threadIdx.x;
    int4 v[16];
    const int4* dp = (const int4*)g_deg + t * 16;
    #pragma unroll
    for (int k = 0; k < 16; k++) v[k] = dp[k];
    int sum = 0;
    #pragma unroll
    for (int k = 0; k < 16; k++) sum += v[k].x + v[k].y + v[k].z + v[k].w;
    __shared__ int part[256];
    part[t] = sum;
    __syncthreads();
    for (int s = 1; s < 256; s <<= 1) {
        int q = (t >= s) ? part[t - s] : 0;
        __syncthreads();
        part[t] += q;
        __syncthreads();
    }
    int run = (t > 0) ? part[t - 1] : 0;
    int4* op = (int4*)g_off + t * 16;
    #pragma unroll
    for (int k = 0; k < 16; k++) {
        int4 o;
        o.x = run; run += v[k].x;
        o.y = run; run += v[k].y;
        o.z = run; run += v[k].z;
        o.w = run; run += v[k].w;
        op[k] = o;
    }
    if (t == 255) g_off[NN] = run;
}
__global__ void scatter_kernel(const int* __restrict__ adj) {
    int i = blockIdx.x * blockDim.x + threadIdx.x;
    if (i < EE) {
        int src = adj[i];
        int dst = adj[EE + i];
        int p = g_off[dst] + atomicAdd(&g_cursor[dst], 1);
        g_esrc[p] = src;
    }
}

// ================= Tensor-core GEMM (bf16x3, cp.async pipeline) =================
__device__ __forceinline__ int smw(int outer, int kw) {
    int line = outer >> 1;
    int M = ((line & 3) << 1) | ((line >> 2) & 1);
    int lc = ((outer & 1) << 2) + (kw >> 1);
    return line * 32 + (((lc ^ M) << 2) | ((kw & 1) << 1));
}
__device__ __forceinline__ void mma16816(float* d, const uint32_t* a,
                                         const uint32_t* b) {
    asm volatile(
        "mma.sync.aligned.m16n8k16.row.col.f32.bf16.bf16.f32 "
        "{%0,%1,%2,%3}, {%4,%5,%6,%7}, {%8,%9}, {%0,%1,%2,%3};\n"
        : "+f"(d[0]), "+f"(d[1]), "+f"(d[2]), "+f"(d[3])
        : "r"(a[0]), "r"(a[1]), "r"(a[2]), "r"(a[3]),
          "r"(b[0]), "r"(b[1]));
}
__device__ __forceinline__ uint32_t smem_u32(const void* p) {
    uint32_t a;
    asm("{ .reg .u64 t; cvta.to.shared.u64 t, %1; cvt.u32.u64 %0, t; }"
        : "=r"(a) : "l"(p));
    return a;
}
__device__ __forceinline__ void cp16(uint32_t dst, const void* src) {
    asm volatile("cp.async.cg.shared.global [%0], [%1], 16;"
                 :: "r"(dst), "l"(src));
}
#define CP_COMMIT() asm volatile("cp.async.commit_group;" ::: "memory")
#define STG_BYTES 16384
#define NSTG 4

__device__ __forceinline__ void fill_stage(
    const uint32_t* __restrict__ Ap, const uint4* __restrict__ Bp,
    int brow, int bcol, int lda, int N, int k0, int tid, uint32_t sbase)
{
    int c4 = tid & 3;
    #pragma unroll
    for (int f = 0; f < 2; f++) {
        int row = (tid >> 2) + 64 * f;
        cp16(sbase + 4 * smw(row, 2 * c4),
             Ap + (size_t)(brow + row) * lda + k0 + 4 * c4);
    }
    int tc = tid >> 6;
    int m  = tid & 63;
    const uint4* bp = Bp + (size_t)((k0 >> 2) + tc) * N + bcol + 2 * m;
    uint32_t bB = sbase + 8192;
    cp16(bB + 4 * smw(2 * m,     2 * tc), bp);
    cp16(bB + 4 * smw(2 * m + 1, 2 * tc), bp + 1);
}

// OUT_MODE: 0 = fp32 write, 1 = packed split-bf16 w/ bias+relu, 2 = fp32 accumulate
template <int OUT_MODE>
__global__ __launch_bounds__(256, 2) void tgemm_p_kernel(
    const uint32_t* __restrict__ Ap, const uint4* __restrict__ Bp,
    const float* __restrict__ bias, void* __restrict__ Cout,
    int M, int N, int K, int lda)
{
    extern __shared__ uint32_t dynsm[];
    const uint32_t sb = smem_u32(dynsm);

    const int tid  = threadIdx.x;
    const int lane = tid & 31;
    const int wid  = tid >> 5;
    const int wm   = wid & 1;
    const int wn   = wid >> 1;
    const int brow = blockIdx.y * 128;
    const int bcol = blockIdx.x * 128;

    float acc[4][4][4];
    #pragma unroll
    for (int i = 0; i < 4; i++)
        #pragma unroll
        for (int j = 0; j < 4; j++)
            #pragma unroll
            for (int q = 0; q < 4; q++) acc[i][j][q] = 0.f;

    const int iters = K >> 4;

    #pragma unroll
    for (int s = 0; s < NSTG - 1; s++) {
        if (s < iters) {
            fill_stage(Ap, Bp, brow, bcol, lda, N, s << 4, tid, sb + s * STG_BYTES);
            CP_COMMIT();
        }
    }

    const int c  = lane & 3;
    const int r4 = lane >> 2;
    const int offA0 = smw(r4, c);
    const int offA1 = smw(8 + r4, c);
    const int offA2 = smw(r4, c + 4);
    const int offA3 = smw(8 + r4, c + 4);

    for (int it = 0; it < iters; ++it) {
        int rem = iters - 1 - it;
        if (rem >= 2)      asm volatile("cp.async.wait_group 2;" ::: "memory");
        else if (rem == 1) asm volatile("cp.async.wait_group 1;" ::: "memory");
        else               asm volatile("cp.async.wait_group 0;" ::: "memory");
        __syncthreads();

        uint32_t* buf  = dynsm + (it & (NSTG - 1)) * 4096;
        uint32_t* Abuf = buf;
        uint32_t* Bbuf = buf + 2048;

        uint2 bfr[4][2];
        #pragma unroll
        for (int ni = 0; ni < 4; ni++) {
            int base = wn * 512;
            bfr[ni][0] = *(const uint2*)&Bbuf[base + smw(ni * 8 + r4, c)];
            bfr[ni][1] = *(const uint2*)&Bbuf[base + smw(ni * 8 + r4, c + 4)];
        }
        #pragma unroll
        for (int mi = 0; mi < 4; mi++) {
            int base = (wm * 64 + mi * 16) * 16;
            uint2 a0 = *(const uint2*)&Abuf[base + offA0];
            uint2 a1 = *(const uint2*)&Abuf[base + offA1];
            uint2 a2 = *(const uint2*)&Abuf[base + offA2];
            uint2 a3 = *(const uint2*)&Abuf[base + offA3];
            uint32_t ah[4] = {a0.x, a1.x, a2.x, a3.x};
            uint32_t al[4] = {a0.y, a1.y, a2.y, a3.y};
            #pragma unroll
            for (int ni = 0; ni < 4; ni++) {
                uint32_t bh[2] = {bfr[ni][0].x, bfr[ni][1].x};
                uint32_t bl[2] = {bfr[ni][0].y, bfr[ni][1].y};
                mma16816(acc[mi][ni], ah, bh);
                mma16816(acc[mi][ni], ah, bl);
                mma16816(acc[mi][ni], al, bh);
            }
        }

        if (it + NSTG - 1 < iters) {
            fill_stage(Ap, Bp, brow, bcol, lda, N, (it + NSTG - 1) << 4, tid,
                       sb + ((it + NSTG - 1) & (NSTG - 1)) * STG_BYTES);
            CP_COMMIT();
        }
    }

    #pragma unroll
    for (int mi = 0; mi < 4; mi++) {
        int row = brow + wm * 64 + mi * 16 + r4;
        #pragma unroll
        for (int ni = 0; ni < 4; ni++) {
            int col = bcol + wn * 32 + ni * 8 + 2 * c;
            float2 v0 = make_float2(acc[mi][ni][0], acc[mi][ni][1]);
            float2 v1 = make_float2(acc[mi][ni][2], acc[mi][ni][3]);
            if (OUT_MODE == 1) {
                float2 bb = *(const float2*)(bias + col);
                v0.x = fmaxf(v0.x + bb.x, 0.f); v0.y = fmaxf(v0.y + bb.y, 0.f);
                v1.x = fmaxf(v1.x + bb.x, 0.f); v1.y = fmaxf(v1.y + bb.y, 0.f);
                uint2 w0, w1;
                split_pack(v0.x, v0.y, w0.x, w0.y);
                split_pack(v1.x, v1.y, w1.x, w1.y);
                uint32_t* P = (uint32_t*)Cout;
                *(uint2*)(P + (size_t)row * N + col)       = w0;
                *(uint2*)(P + (size_t)(row + 8) * N + col) = w1;
            } else {
                float* C = (float*)Cout;
                float* c0 = C + (size_t)row * N + col;
                float* c1 = C + (size_t)(row + 8) * N + col;
                if (OUT_MODE == 2) {
                    float2 o0 = *(float2*)c0;
                    float2 o1 = *(float2*)c1;
                    v0.x += o0.x; v0.y += o0.y;
                    v1.x += o1.x; v1.y += o1.y;
                }
                *(float2*)c0 = v0;
                *(float2*)c1 = v1;
            }
        }
    }
}

// ---------------- attention scalars from packed h via projections ----------------
__global__ void al1p_kernel() {
    int n = (blockIdx.x * blockDim.x + threadIdx.x) >> 5;
    if (n >= NN) return;
    int lane = threadIdx.x & 31;
    const uint2* row = (const uint2*)(g_h0p + (size_t)n * H1C);
    float s0 = 0.f, s1 = 0.f, d0 = 0.f, d1 = 0.f;
    for (int i = lane; i < 128; i += 32) {
        uint2 w = row[i];
        float x0 = bf_lo(w.x) + bf_lo(w.y);
        float x1 = bf_hi(w.x) + bf_hi(w.y);
        float4 p0 = g_P1[2 * i];
        float4 p1 = g_P1[2 * i + 1];
        s0 += x0 * p0.x + x1 * p1.x;
        s1 += x0 * p0.y + x1 * p1.y;
        d0 += x0 * p0.z + x1 * p1.z;
        d1 += x0 * p0.w + x1 * p1.w;
    }
    #pragma unroll
    for (int o = 16; o; o >>= 1) {
        s0 += __shfl_down_sync(0xffffffffu, s0, o);
        s1 += __shfl_down_sync(0xffffffffu, s1, o);
        d0 += __shfl_down_sync(0xffffffffu, d0, o);
        d1 += __shfl_down_sync(0xffffffffu, d1, o);
    }
    if (lane == 0) ((float4*)g_al1)[n] = make_float4(s0, s1, d0, d1);
}

// al2 contribution from one K-half of h1p; out = g_al2a or g_al2b
__global__ void al2h_kernel(int half, float2* __restrict__ outv) {
    int n = (blockIdx.x * blockDim.x + threadIdx.x) >> 5;
    if (n >= NN) return;
    int lane = threadIdx.x & 31;
    const uint2* row = (const uint2*)(g_h1p + (size_t)n * DD + half * H1C);
    const float2* P = g_P2 + half * H1C;
    float s = 0.f, d = 0.f;
    for (int i = lane; i < 128; i += 32) {
        uint2 w = row[i];
        float x0 = bf_lo(w.x) + bf_lo(w.y);
        float x1 = bf_hi(w.x) + bf_hi(w.y);
        float2 p0 = P[2 * i];
        float2 p1 = P[2 * i + 1];
        s += x0 * p0.x + x1 * p1.x;
        d += x0 * p0.y + x1 * p1.y;
    }
    #pragma unroll
    for (int o = 16; o; o >>= 1) {
        s += __shfl_down_sync(0xffffffffu, s, o);
        d += __shfl_down_sync(0xffffffffu, d, o);
    }
    if (lane == 0) outv[n] = make_float2(s, d);
}

__device__ __forceinline__ float lrelu(float x) {
    return x > 0.f ? x : NEG_SLOPE * x;
}

// ---------------- edge softmax ----------------
__global__ void alpha1_kernel() {
    int n = (blockIdx.x * blockDim.x + threadIdx.x) >> 5;
    if (n >= NN) return;
    int lane = threadIdx.x & 31;
    int o = g_off[n];
    int cnt = g_off[n + 1] - o;
    float dd0 = g_al1[n * 4 + 2];
    float dd1 = g_al1[n * 4 + 3];

    float m0 = -1e30f, m1 = -1e30f;
    for (int i = lane; i <= cnt; i += 32) {
        int s = (i < cnt) ? g_esrc[o + i] : n;
        m0 = fmaxf(m0, lrelu(g_al1[s * 4 + 0] + dd0));
        m1 = fmaxf(m1, lrelu(g_al1[s * 4 + 1] + dd1));
    }
    #pragma unroll
    for (int x = 16; x; x >>= 1) {
        m0 = fmaxf(m0, __shfl_xor_sync(0xffffffffu, m0, x));
        m1 = fmaxf(m1, __shfl_xor_sync(0xffffffffu, m1, x));
    }
    float sum0 = 0.f, sum1 = 0.f;
    for (int i = lane; i <= cnt; i += 32) {
        int s = (i < cnt) ? g_esrc[o + i] : n;
        sum0 += expf(lrelu(g_al1[s * 4 + 0] + dd0) - m0);
        sum1 += expf(lrelu(g_al1[s * 4 + 1] + dd1) - m1);
    }
    #pragma unroll
    for (int x = 16; x; x >>= 1) {
        sum0 += __shfl_xor_sync(0xffffffffu, sum0, x);
        sum1 += __shfl_xor_sync(0xffffffffu, sum1, x);
    }
    float inv0 = 1.f / (sum0 + 1e-16f);
    float inv1 = 1.f / (sum1 + 1e-16f);
    for (int i = lane; i <= cnt; i += 32) {
        int s = (i < cnt) ? g_esrc[o + i] : n;
        float a0 = expf(lrelu(g_al1[s * 4 + 0] + dd0) - m0) * inv0;
        float a1 = expf(lrelu(g_al1[s * 4 + 1] + dd1) - m1) * inv1;
        if (i < cnt) {
            g_alpha1[(size_t)(o + i) * 2 + 0] = a0;
            g_alpha1[(size_t)(o + i) * 2 + 1] = a1;
        } else {
            g_salpha1[n * 2 + 0] = a0;
            g_salpha1[n * 2 + 1] = a1;
        }
    }
}

__global__ void alpha2_kernel() {
    int n = (blockIdx.x * blockDim.x + threadIdx.x) >> 5;
    if (n >= NN) return;
    int lane = threadIdx.x & 31;
    int o = g_off[n];
    int cnt = g_off[n + 1] - o;
    float2 va = g_al2a[n];
    float2 vb = g_al2b[n];
    float dd = va.y + vb.y;

    float m = -1e30f;
    for (int i = lane; i <= cnt; i += 32) {
        int s = (i < cnt) ? g_esrc[o + i] : n;
        float sv = g_al2a[s].x + g_al2b[s].x;
        m = fmaxf(m, lrelu(sv + dd));
    }
    #pragma unroll
    for (int x = 16; x; x >>= 1)
        m = fmaxf(m, __shfl_xor_sync(0xffffffffu, m, x));
    float sum = 0.f;
    for (int i = lane; i <= cnt; i += 32) {
        int s = (i < cnt) ? g_esrc[o + i] : n;
        float sv = g_al2a[s].x + g_al2b[s].x;
        sum += expf(lrelu(sv + dd) - m);
    }
    #pragma unroll
    for (int x = 16; x; x >>= 1)
        sum += __shfl_xor_sync(0xffffffffu, sum, x);
    float inv = 1.f / (sum + 1e-16f);
    for (int i = lane; i <= cnt; i += 32) {
        int s = (i < cnt) ? g_esrc[o + i] : n;
        float sv = g_al2a[s].x + g_al2b[s].x;
        float a = expf(lrelu(sv + dd) - m) * inv;
        if (i < cnt) g_alpha2[o + i] = a;
        else g_salpha2[n] = a;
    }
}

// ---------------- aggregation halves ----------------
__global__ __launch_bounds__(64) void agg1h_kernel(const float* __restrict__ b1,
                                                   int head) {
    int n = blockIdx.x;
    int tid = threadIdx.x;
    int o = g_off[n];
    int cnt = g_off[n + 1] - o;

    __shared__ int   ssrc[64];
    __shared__ float sal[64];

    const float* gbase = g_g1 + (size_t)head * H1C;
    float4 acc = make_float4(0.f, 0.f, 0.f, 0.f);
    for (int base = 0; base < cnt; base += 64) {
        int m = min(64, cnt - base);
        if (tid < m) {
            int e = o + base + tid;
            ssrc[tid] = g_esrc[e];
            sal[tid] = g_alpha1[(size_t)e * 2 + head];
        }
        __syncthreads();
        #pragma unroll 4
        for (int j = 0; j < m; j++) {
            float a = sal[j];
            float4 v = ((const float4*)(gbase + (size_t)ssrc[j] * DD))[tid];
            acc.x = fmaf(a, v.x, acc.x);
            acc.y = fmaf(a, v.y, acc.y);
            acc.z = fmaf(a, v.z, acc.z);
            acc.w = fmaf(a, v.w, acc.w);
        }
        __syncthreads();
    }
    {
        float a = g_salpha1[n * 2 + head];
        float4 v = ((const float4*)(gbase + (size_t)n * DD))[tid];
        acc.x = fmaf(a, v.x, acc.x);
        acc.y = fmaf(a, v.y, acc.y);
        acc.z = fmaf(a, v.z, acc.z);
        acc.w = fmaf(a, v.w, acc.w);
    }
    float4 bb = ((const float4*)(b1 + head * H1C))[tid];
    acc.x = fmaxf(acc.x + bb.x, 0.f);
    acc.y = fmaxf(acc.y + bb.y, 0.f);
    acc.z = fmaxf(acc.z + bb.z, 0.f);
    acc.w = fmaxf(acc.w + bb.w, 0.f);
    uint4 w;
    split_pack(acc.x, acc.y, w.x, w.y);
    split_pack(acc.z, acc.w, w.z, w.w);
    *(uint4*)(g_h1p + (size_t)n * DD + head * H1C + 4 * tid) = w;
}

__global__ __launch_bounds__(64) void agg2h_kernel(const float* __restrict__ b2,
                                                   float* __restrict__ out,
                                                   int half) {
    int n = blockIdx.x;
    int tid = threadIdx.x;
    int o = g_off[n];
    int cnt = g_off[n + 1] - o;

    __shared__ int   ssrc[64];
    __shared__ float sal[64];

    const float* gbase = g_g2 + (size_t)half * H1C;
    float4 acc = make_float4(0.f, 0.f, 0.f, 0.f);
    for (int base = 0; base < cnt; base += 64) {
        int m = min(64, cnt - base);
        if (tid < m) {
            ssrc[tid] = g_esrc[o + base + tid];
            sal[tid] = g_alpha2[o + base + tid];
        }
        __syncthreads();
        #pragma unroll 4
        for (int j = 0; j < m; j++) {
            float a = sal[j];
            float4 v = ((const float4*)(gbase + (size_t)ssrc[j] * DD))[tid];
            acc.x = fmaf(a, v.x, acc.x);
            acc.y = fmaf(a, v.y, acc.y);
            acc.z = fmaf(a, v.z, acc.z);
            acc.w = fmaf(a, v.w, acc.w);
        }
        __syncthreads();
    }
    {
        float a = g_salpha2[n];
        float4 v = ((const float4*)(gbase + (size_t)n * DD))[tid];
        acc.x = fmaf(a, v.x, acc.x);
        acc.y = fmaf(a, v.y, acc.y);
        acc.z = fmaf(a, v.z, acc.z);
        acc.w = fmaf(a, v.w, acc.w);
    }
    float4 bb = ((const float4*)(b2 + half * H1C))[tid];
    acc.x = fmaxf(acc.x + bb.x, 0.f);
    acc.y = fmaxf(acc.y + bb.y, 0.f);
    acc.z = fmaxf(acc.z + bb.z, 0.f);
    acc.w = fmaxf(acc.w + bb.w, 0.f);
    *(float4*)(out + (size_t)n * DD + half * H1C + 4 * tid) = acc;
}

__global__ void join_kernel() {}

// ---------------- launcher ----------------
template <typename T>
static T* sym_p(const void* sym) {
    void* p = nullptr;
    cudaGetSymbolAddress(&p, sym);
    return (T*)p;
}

extern "C" void kernel_launch(void* const* d_in, const int* in_sizes, int n_in,
                              void* d_out, int out_size) {
    const float* x      = (const float*)d_in[0];
    const int*   adj    = (const int*)d_in[1];
    const float* W_fc   = (const float*)d_in[2];
    const float* b_fc   = (const float*)d_in[3];
    const float* W1     = (const float*)d_in[4];
    const float* a1_src = (const float*)d_in[5];
    const float* a1_dst = (const float*)d_in[6];
    const float* b1     = (const float*)d_in[7];
    const float* W2     = (const float*)d_in[8];
    const float* a2_src = (const float*)d_in[9];
    const float* a2_dst = (const float*)d_in[10];
    const float* b2     = (const float*)d_in[11];
    float* out = (float*)d_out;

    uint32_t* p_xp  = sym_p<uint32_t>(g_xp);
    uint32_t* p_h0p = sym_p<uint32_t>(g_h0p);
    uint32_t* p_h1p = sym_p<uint32_t>(g_h1p);
    float*    p_g1  = sym_p<float>(g_g1);
    float*    p_g2  = sym_p<float>(g_g2);
    uint4*    p_wfc = sym_p<uint4>(g_wfcp);
    uint4*    p_w1  = sym_p<uint4>(g_w1p);
    uint4*    p_w2  = sym_p<uint4>(g_w2p);
    float2*   p_a2a = sym_p<float2>(g_al2a);
    float2*   p_a2b = sym_p<float2>(g_al2b);

    const int dyn = NSTG * STG_BYTES;   // 64 KB
    cudaFuncSetAttribute(tgemm_p_kernel<0>,
                         cudaFuncAttributeMaxDynamicSharedMemorySize, dyn);
    cudaFuncSetAttribute(tgemm_p_kernel<1>,
                         cudaFuncAttributeMaxDynamicSharedMemorySize, dyn);
    cudaFuncSetAttribute(tgemm_p_kernel<2>,
                         cudaFuncAttributeMaxDynamicSharedMemorySize, dyn);

    // ---- fork s1: projections, W1+W2 packs, CSR build
    cudaEventRecord(g_evF, 0);
    cudaStreamWaitEvent(g_s1, g_evF, 0);
    pack_b_kernel<<<((H1C / 4) * DD + 255) / 256, 256, 0, g_s1>>>(W1, p_w1, H1C, DD);
    cudaEventRecord(g_evWP, g_s1);
    proj1_kernel<<<(H1C * 32 + 255) / 256, 256, 0, g_s1>>>(W1, a1_src, a1_dst);
    proj2_kernel<<<(DD * 32 + 255) / 256, 256, 0, g_s1>>>(W2, a2_src, a2_dst);
    pack_b_kernel<<<((DD / 4) * DD + 255) / 256, 256, 0, g_s1>>>(W2, p_w2, DD, DD);
    zero_kernel<<<(NN + 255) / 256, 256, 0, g_s1>>>();
    count_kernel<<<(EE + 255) / 256, 256, 0, g_s1>>>(adj);
    scan_kernel<<<1, 256, 0, g_s1>>>();
    scatter_kernel<<<(EE + 255) / 256, 256, 0, g_s1>>>(adj);

    // ---- main: packs + GEMM1
    pack_a_kernel<<<(NN * H1C / 2 + 255) / 256, 256>>>(x, p_xp, NN * H1C / 2);
    pack_b_kernel<<<((H1C / 4) * H1C + 255) / 256, 256>>>(W_fc, p_wfc, H1C, H1C);
    tgemm_p_kernel<1><<<dim3(H1C / 128, NN / 128), 256, dyn>>>(
        p_xp, p_wfc, b_fc, p_h0p, NN, H1C, H1C, H1C);
    cudaEventRecord(g_evG1, 0);

    // s1: al1 + alpha1 concurrent with GEMM2a/b
    cudaStreamWaitEvent(g_s1, g_evG1, 0);
    al1p_kernel<<<(NN * 32 + 255) / 256, 256, 0, g_s1>>>();
    alpha1_kernel<<<(NN * 32 + 255) / 256, 256, 0, g_s1>>>();
    cudaEventRecord(g_evJ1, g_s1);

    // main: GEMM2 column halves (needs W1 pack from s1)
    cudaStreamWaitEvent(0, g_evWP, 0);
    tgemm_p_kernel<0><<<dim3(2, NN / 128), 256, dyn>>>(
        p_h0p, p_w1, nullptr, p_g1, NN, DD, H1C, H1C);
    cudaEventRecord(g_evG2a, 0);
    tgemm_p_kernel<0><<<dim3(2, NN / 128), 256, dyn>>>(
        p_h0p, p_w1 + H1C, nullptr, p_g1 + H1C, NN, DD, H1C, H1C);

    // s1: agg1 head0 (h1p K-half0), then G3(N0,K0)
    cudaStreamWaitEvent(g_s1, g_evG2a, 0);
    agg1h_kernel<<<NN, 64, 0, g_s1>>>(b1, 0);
    cudaEventRecord(g_evH0, g_s1);
    tgemm_p_kernel<0><<<dim3(2, NN / 128), 256, dyn, g_s1>>>(
        p_h1p, p_w2, nullptr, p_g2, NN, DD, H1C, DD);

    // s2: al2 half0 as soon as h1p K-half0 exists
    cudaStreamWaitEvent(g_s2, g_evH0, 0);
    al2h_kernel<<<(NN * 32 + 255) / 256, 256, 0, g_s2>>>(0, p_a2a);

    // main: agg1 head1 (after GEMM2b on main; alpha1 via evJ1)
    cudaStreamWaitEvent(0, g_evJ1, 0);
    agg1h_kernel<<<NN, 64>>>(b1, 1);
    cudaEventRecord(g_evH1, 0);

    // s2: al2 half1 + alpha2
    cudaStreamWaitEvent(g_s2, g_evH1, 0);
    al2h_kernel<<<(NN * 32 + 255) / 256, 256, 0, g_s2>>>(1, p_a2b);
    alpha2_kernel<<<(NN * 32 + 255) / 256, 256, 0, g_s2>>>();
    cudaEventRecord(g_evJ2, g_s2);

    // s1: G3(N0,K1) accumulate — needs h1p K-half1
    cudaStreamWaitEvent(g_s1, g_evH1, 0);
    tgemm_p_kernel<2><<<dim3(2, NN / 128), 256, dyn, g_s1>>>(
        p_h1p + H1C, p_w2 + (size_t)(H1C / 4) * DD, nullptr, p_g2,
        NN, DD, H1C, DD);

    // main: G3(N1,K0) then G3(N1,K1) accumulate
    cudaStreamWaitEvent(0, g_evH0, 0);
    tgemm_p_kernel<0><<<dim3(2, NN / 128), 256, dyn>>>(
        p_h1p, p_w2 + H1C, nullptr, p_g2 + H1C, NN, DD, H1C, DD);
    tgemm_p_kernel<2><<<dim3(2, NN / 128), 256, dyn>>>(
        p_h1p + H1C, p_w2 + (size_t)(H1C / 4) * DD + H1C, nullptr, p_g2 + H1C,
        NN, DD, H1C, DD);

    // s1: agg2 half0 (g2 N0 complete on s1) — needs alpha2
    cudaStreamWaitEvent(g_s1, g_evJ2, 0);
    agg2h_kernel<<<NN, 64, 0, g_s1>>>(b2, out, 0);
    cudaEventRecord(g_evA2H0, g_s1);

    // main: agg2 half1, then join all branches
    cudaStreamWaitEvent(0, g_evJ2, 0);
    agg2h_kernel<<<NN, 64>>>(b2, out, 1);
    cudaStreamWaitEvent(0, g_evA2H0, 0);
    join_kernel<<<1, 32>>>();
}